// round 1
// baseline (speedup 1.0000x reference)
#include <cuda_runtime.h>
#include <math.h>

#define BSZ 4
#define TSZ 2048
#define CSZ 768
#define NH  16
#define HD  48
#define MSZ (BSZ*TSZ)   // 8192

// Scratch (device globals -> no allocation)
__device__ float g_q[BSZ*NH*TSZ*HD];
__device__ float g_k[BSZ*NH*TSZ*HD];
__device__ float g_v[BSZ*NH*TSZ*HD];
__device__ float g_ctx[BSZ*TSZ*CSZ];

// ---------------------------------------------------------------------------
// GEMM: C[m,n] = sum_k A[m,k] * W[n,k] + bias[n]
// A: [M, K] row-major, W: [N, K] row-major (so this is x @ W^T)
// scatter==0: out[m*CSZ + n]
// scatter==1: out[((b*NH+h)*TSZ + t)*HD + dd]  (b=m/T, t=m%T, h=n/HD, dd=n%HD)
// ---------------------------------------------------------------------------
#define BM 64
#define BN 64
#define BKK 16

__global__ void __launch_bounds__(256)
gemm_kernel(const float* __restrict__ A, const float* __restrict__ W,
            const float* __restrict__ bias, float* __restrict__ out, int scatter)
{
    __shared__ float As[BKK][BM];
    __shared__ float Bs[BKK][BN];

    const int tid = threadIdx.x;
    const int tx = tid & 15;        // 0..15
    const int ty = tid >> 4;        // 0..15
    const int m0 = blockIdx.y * BM;
    const int n0 = blockIdx.x * BN;

    float acc[4][4] = {};

    const int lrow = tid >> 2;          // 0..63
    const int lk4  = (tid & 3) << 2;    // 0,4,8,12
    const int K = CSZ;

    for (int k0 = 0; k0 < K; k0 += BKK) {
        float4 av = *reinterpret_cast<const float4*>(&A[(m0 + lrow) * K + k0 + lk4]);
        float4 bv = *reinterpret_cast<const float4*>(&W[(n0 + lrow) * K + k0 + lk4]);
        As[lk4 + 0][lrow] = av.x; As[lk4 + 1][lrow] = av.y;
        As[lk4 + 2][lrow] = av.z; As[lk4 + 3][lrow] = av.w;
        Bs[lk4 + 0][lrow] = bv.x; Bs[lk4 + 1][lrow] = bv.y;
        Bs[lk4 + 2][lrow] = bv.z; Bs[lk4 + 3][lrow] = bv.w;
        __syncthreads();

        #pragma unroll
        for (int kk = 0; kk < BKK; kk++) {
            float4 a  = *reinterpret_cast<const float4*>(&As[kk][ty << 2]);
            float4 bb = *reinterpret_cast<const float4*>(&Bs[kk][tx << 2]);
            float ar[4] = {a.x, a.y, a.z, a.w};
            float br[4] = {bb.x, bb.y, bb.z, bb.w};
            #pragma unroll
            for (int i = 0; i < 4; i++)
                #pragma unroll
                for (int j = 0; j < 4; j++)
                    acc[i][j] += ar[i] * br[j];
        }
        __syncthreads();
    }

    #pragma unroll
    for (int i = 0; i < 4; i++) {
        int m = m0 + (ty << 2) + i;
        #pragma unroll
        for (int j = 0; j < 4; j++) {
            int n = n0 + (tx << 2) + j;
            float val = acc[i][j] + bias[n];
            if (!scatter) {
                out[m * CSZ + n] = val;
            } else {
                int b = m / TSZ, t = m % TSZ;
                int h = n / HD,  dd = n % HD;
                out[((b * NH + h) * TSZ + t) * HD + dd] = val;
            }
        }
    }
}

// ---------------------------------------------------------------------------
// RoPE, applied in place to g_q and g_k ([B*H*T, HD] rows).
// pair (i, i+24), angle = t * base^(-2i/48)
// ---------------------------------------------------------------------------
__global__ void __launch_bounds__(256)
rope_kernel()
{
    const int total = BSZ * NH * TSZ * (HD / 2);
    int idx = blockIdx.x * blockDim.x + threadIdx.x;
    if (idx >= total) return;
    int i   = idx % (HD / 2);
    int row = idx / (HD / 2);
    int t   = row % TSZ;

    // inv_freq = exp(-(i/24) * ln(10000))
    float inv_freq = expf(-((float)i / 24.0f) * 9.210340371976184f);
    float ang = (float)t * inv_freq;
    float s, c;
    sincosf(ang, &s, &c);

    float* q = g_q + row * HD;
    float* k = g_k + row * HD;
    float q1 = q[i], q2 = q[i + 24];
    q[i]      = q1 * c - q2 * s;
    q[i + 24] = q2 * c + q1 * s;
    float k1 = k[i], k2 = k[i + 24];
    k[i]      = k1 * c - k2 * s;
    k[i + 24] = k2 * c + k1 * s;
}

// ---------------------------------------------------------------------------
// Causal flash attention. 1 thread = 1 query row. Block = 128 threads.
// grid = (T/128, B*H). K/V tiles (64 rows x 48) staged in smem.
// Online softmax with lazy rescale (rescale only on new max).
// Output -> g_ctx in [B, T, C] layout.
// ---------------------------------------------------------------------------
#define AQ 128
#define AK 64

__global__ void __launch_bounds__(128)
attn_kernel(const float* __restrict__ mask)
{
    __shared__ float4 Ks[AK * 12];
    __shared__ float4 Vs[AK * 12];
    __shared__ float  Ms[AK];

    const int bh = blockIdx.y;
    const int b  = bh >> 4;       // /NH
    const int h  = bh & 15;
    const int qi = blockIdx.x * AQ + threadIdx.x;   // query position in [0, T)

    const float* qp = g_q + (bh * TSZ + qi) * HD;
    float4 q4[12];
    #pragma unroll
    for (int w = 0; w < 12; w++)
        q4[w] = *reinterpret_cast<const float4*>(qp + 4 * w);

    float4 o4[12];
    #pragma unroll
    for (int w = 0; w < 12; w++) o4[w] = make_float4(0.f, 0.f, 0.f, 0.f);

    float m = -1e30f, l = 0.f;
    const float scale = 0.14433756729740643f;   // 1/sqrt(48)

    const int ntile = (blockIdx.x + 1) * (AQ / AK);
    const float4* kbase = reinterpret_cast<const float4*>(g_k + bh * TSZ * HD);
    const float4* vbase = reinterpret_cast<const float4*>(g_v + bh * TSZ * HD);
    const float*  mrow  = mask + b * TSZ;

    for (int kt = 0; kt < ntile; kt++) {
        __syncthreads();
        const float4* ksrc = kbase + kt * AK * 12;
        const float4* vsrc = vbase + kt * AK * 12;
        for (int i = threadIdx.x; i < AK * 12; i += AQ) {
            Ks[i] = ksrc[i];
            Vs[i] = vsrc[i];
        }
        if (threadIdx.x < AK)
            Ms[threadIdx.x] = (1.0f - mrow[kt * AK + threadIdx.x]) * -10000.0f;
        __syncthreads();

        int jmax = qi - kt * AK + 1;
        if (jmax > AK) jmax = AK;

        for (int j = 0; j < jmax; j++) {
            const float4* kr = &Ks[j * 12];
            float s0 = 0.f, s1 = 0.f, s2 = 0.f, s3 = 0.f;
            #pragma unroll
            for (int w = 0; w < 12; w++) {
                float4 kv = kr[w];
                s0 += q4[w].x * kv.x;
                s1 += q4[w].y * kv.y;
                s2 += q4[w].z * kv.z;
                s3 += q4[w].w * kv.w;
            }
            float s = (s0 + s1) + (s2 + s3);
            s = s * scale + Ms[j];

            if (s > m) {                     // rare after warm-up
                float corr = __expf(m - s);
                m = s;
                l *= corr;
                #pragma unroll
                for (int w = 0; w < 12; w++) {
                    o4[w].x *= corr; o4[w].y *= corr;
                    o4[w].z *= corr; o4[w].w *= corr;
                }
            }
            float p = __expf(s - m);
            l += p;

            const float4* vr = &Vs[j * 12];
            #pragma unroll
            for (int w = 0; w < 12; w++) {
                float4 vv = vr[w];
                o4[w].x += p * vv.x; o4[w].y += p * vv.y;
                o4[w].z += p * vv.z; o4[w].w += p * vv.w;
            }
        }
    }

    const float inv_l = 1.0f / l;
    float* op = g_ctx + (b * TSZ + qi) * CSZ + h * HD;
    #pragma unroll
    for (int w = 0; w < 12; w++) {
        float4 r;
        r.x = o4[w].x * inv_l; r.y = o4[w].y * inv_l;
        r.z = o4[w].z * inv_l; r.w = o4[w].w * inv_l;
        *reinterpret_cast<float4*>(op + 4 * w) = r;
    }
}

// ---------------------------------------------------------------------------
extern "C" void kernel_launch(void* const* d_in, const int* in_sizes, int n_in,
                              void* d_out, int out_size)
{
    const float* X    = (const float*)d_in[0];
    const float* mask = (const float*)d_in[1];
    const float* Wq   = (const float*)d_in[2];
    const float* bq   = (const float*)d_in[3];
    const float* Wk   = (const float*)d_in[4];
    const float* bk   = (const float*)d_in[5];
    const float* Wv   = (const float*)d_in[6];
    const float* bv   = (const float*)d_in[7];
    const float* Wo   = (const float*)d_in[8];
    const float* bo   = (const float*)d_in[9];
    float* out = (float*)d_out;

    float *qb, *kb, *vb, *ctxb;
    cudaGetSymbolAddress((void**)&qb,   g_q);
    cudaGetSymbolAddress((void**)&kb,   g_k);
    cudaGetSymbolAddress((void**)&vb,   g_v);
    cudaGetSymbolAddress((void**)&ctxb, g_ctx);

    dim3 ggrid(CSZ / BN, MSZ / BM);   // (12, 128)
    gemm_kernel<<<ggrid, 256>>>(X, Wq, bq, qb, 1);
    gemm_kernel<<<ggrid, 256>>>(X, Wk, bk, kb, 1);
    gemm_kernel<<<ggrid, 256>>>(X, Wv, bv, vb, 1);

    int rope_total = BSZ * NH * TSZ * (HD / 2);
    rope_kernel<<<(rope_total + 255) / 256, 256>>>();

    dim3 agrid(TSZ / AQ, BSZ * NH);   // (16, 64)
    attn_kernel<<<agrid, 128>>>(mask);

    gemm_kernel<<<ggrid, 256>>>(ctxb, Wo, bo, out, 0);
}

// round 4
// speedup vs baseline: 1.5477x; 1.5477x over previous
#include <cuda_runtime.h>
#include <cuda_bf16.h>
#include <cstdint>
#include <math.h>

#define BSZ 4
#define TSZ 2048
#define CSZ 768
#define NH  16
#define HD  48
#define MSZ (BSZ*TSZ)   // 8192

// ---------------------------------------------------------------------------
// Scratch (device globals -> no allocation)
// ---------------------------------------------------------------------------
__device__ float g_q[BSZ*NH*TSZ*HD];
__device__ float g_k[BSZ*NH*TSZ*HD];
__device__ float g_v[BSZ*NH*TSZ*HD];
__device__ float g_ctx[BSZ*TSZ*CSZ];

__device__ __nv_bfloat16 g_xhi[MSZ*CSZ];
__device__ __nv_bfloat16 g_xlo[MSZ*CSZ];
__device__ __nv_bfloat16 g_chi[MSZ*CSZ];
__device__ __nv_bfloat16 g_clo[MSZ*CSZ];
__device__ __nv_bfloat16 g_whi[4][CSZ*CSZ];
__device__ __nv_bfloat16 g_wlo[4][CSZ*CSZ];

// ---------------------------------------------------------------------------
// PTX helpers (compute_103-safe: mma.sync / ldmatrix / cp.async only)
// ---------------------------------------------------------------------------
__device__ __forceinline__ uint32_t smem_u32(const void* p) {
    uint32_t a;
    asm("{ .reg .u64 t; cvta.to.shared.u64 t, %1; cvt.u32.u64 %0, t; }"
        : "=r"(a) : "l"(p));
    return a;
}
__device__ __forceinline__ void cp_async16(uint32_t s, const void* g) {
    asm volatile("cp.async.ca.shared.global [%0], [%1], 16;" :: "r"(s), "l"(g));
}
#define CP_COMMIT() asm volatile("cp.async.commit_group;" ::: "memory")
#define CP_WAIT(n)  asm volatile("cp.async.wait_group %0;" :: "n"(n) : "memory")

__device__ __forceinline__ void ldmat4(uint32_t addr, uint32_t* r) {
    asm volatile("ldmatrix.sync.aligned.m8n8.x4.shared.b16 {%0,%1,%2,%3}, [%4];"
        : "=r"(r[0]), "=r"(r[1]), "=r"(r[2]), "=r"(r[3]) : "r"(addr));
}
__device__ __forceinline__ void mma_bf16(float* d, const uint32_t* a, const uint32_t* b) {
    asm volatile("mma.sync.aligned.m16n8k16.row.col.f32.bf16.bf16.f32 "
        "{%0,%1,%2,%3}, {%4,%5,%6,%7}, {%8,%9}, {%0,%1,%2,%3};"
        : "+f"(d[0]), "+f"(d[1]), "+f"(d[2]), "+f"(d[3])
        : "r"(a[0]), "r"(a[1]), "r"(a[2]), "r"(a[3]), "r"(b[0]), "r"(b[1]));
}

// ---------------------------------------------------------------------------
// fp32 -> split bf16 (hi + lo)
// ---------------------------------------------------------------------------
__global__ void __launch_bounds__(256)
conv_kernel(const float* __restrict__ in, __nv_bfloat16* __restrict__ hi,
            __nv_bfloat16* __restrict__ lo, int n4)
{
    int i = blockIdx.x * blockDim.x + threadIdx.x;
    if (i >= n4) return;
    float4 x = reinterpret_cast<const float4*>(in)[i];
    __nv_bfloat16 h0 = __float2bfloat16(x.x);
    __nv_bfloat16 h1 = __float2bfloat16(x.y);
    __nv_bfloat16 h2 = __float2bfloat16(x.z);
    __nv_bfloat16 h3 = __float2bfloat16(x.w);
    __nv_bfloat162 hv0; hv0.x = h0; hv0.y = h1;
    __nv_bfloat162 hv1; hv1.x = h2; hv1.y = h3;
    __nv_bfloat162 lv0, lv1;
    lv0.x = __float2bfloat16(x.x - __bfloat162float(h0));
    lv0.y = __float2bfloat16(x.y - __bfloat162float(h1));
    lv1.x = __float2bfloat16(x.z - __bfloat162float(h2));
    lv1.y = __float2bfloat16(x.w - __bfloat162float(h3));
    reinterpret_cast<__nv_bfloat162*>(hi)[2*i]   = hv0;
    reinterpret_cast<__nv_bfloat162*>(hi)[2*i+1] = hv1;
    reinterpret_cast<__nv_bfloat162*>(lo)[2*i]   = lv0;
    reinterpret_cast<__nv_bfloat162*>(lo)[2*i+1] = lv1;
}

// ---------------------------------------------------------------------------
// mma.sync split-bf16 GEMM: out[m,n] = sum_k A[m,k]*W[n,k] + bias[n]
// A: [8192,768], W: [768,768]. CTA tile 128x64, 4 warps of 64x32,
// K-chunk 32, cp.async double-buffered. D = AhiWhi + AhiWlo + AloWhi.
// ---------------------------------------------------------------------------
#define CTA_M 128
#define CTA_N 64
#define KCH   32
#define NCH   (CSZ/KCH)        // 24
#define STRD  80               // bytes per smem row: 64B data + 16B pad
#define A_BYTES (CTA_M*STRD)   // 10240
#define W_BYTES (CTA_N*STRD)   // 5120
#define STAGE_BYTES (2*A_BYTES + 2*W_BYTES)  // 30720
#define GEMM_SMEM (2*STAGE_BYTES)            // 61440

__global__ void __launch_bounds__(128)
gemm_mma_kernel(const __nv_bfloat16* __restrict__ Ahi,
                const __nv_bfloat16* __restrict__ Alo,
                const __nv_bfloat16* __restrict__ Whi,
                const __nv_bfloat16* __restrict__ Wlo,
                const float* __restrict__ bias,
                float* __restrict__ out, int scatter)
{
    extern __shared__ char smem[];
    const int tid  = threadIdx.x;
    const int wid  = tid >> 5;
    const int lane = tid & 31;
    const int m0 = blockIdx.y * CTA_M;
    const int n0 = blockIdx.x * CTA_N;
    const int wm = (wid & 1) * 64;     // warp m offset in CTA tile
    const int wn = (wid >> 1) * 32;    // warp n offset
    const uint32_t sbase = smem_u32(smem);

    float acc[4][4][4];
    #pragma unroll
    for (int a = 0; a < 4; a++)
        #pragma unroll
        for (int b = 0; b < 4; b++)
            #pragma unroll
            for (int c = 0; c < 4; c++) acc[a][b][c] = 0.f;

    auto load_stage = [&](int kc, int s) {
        uint32_t sb = sbase + s * STAGE_BYTES;
        int kk = kc * KCH;
        #pragma unroll
        for (int i = 0; i < 8; i++) {            // A hi+lo: 1024 x 16B
            int idx = i * 128 + tid;
            int part = idx >> 9, rem = idx & 511, row = rem >> 2, seg = rem & 3;
            const __nv_bfloat16* src =
                (part ? Alo : Ahi) + (size_t)(m0 + row) * CSZ + kk + seg * 8;
            cp_async16(sb + part * A_BYTES + row * STRD + seg * 16, src);
        }
        #pragma unroll
        for (int i = 0; i < 4; i++) {            // W hi+lo: 512 x 16B
            int idx = i * 128 + tid;
            int part = idx >> 8, rem = idx & 255, row = rem >> 2, seg = rem & 3;
            const __nv_bfloat16* src =
                (part ? Wlo : Whi) + (size_t)(n0 + row) * CSZ + kk + seg * 8;
            cp_async16(sb + 2 * A_BYTES + part * W_BYTES + row * STRD + seg * 16, src);
        }
        CP_COMMIT();
    };

    load_stage(0, 0);
    int s = 0;

    const int l15 = lane & 15;
    const int lh16 = (lane >> 4) * 16;                 // A k-half byte offset
    const int brow = ((lane >> 4) << 3) + (lane & 7);  // B row-in-16 group
    const int bk16 = ((lane >> 3) & 1) * 16;           // B k-half byte offset

    for (int kc = 0; kc < NCH; kc++) {
        if (kc + 1 < NCH) { load_stage(kc + 1, s ^ 1); CP_WAIT(1); }
        else             { CP_WAIT(0); }
        __syncthreads();

        uint32_t sb   = sbase + s * STAGE_BYTES;
        uint32_t aHiB = sb;
        uint32_t aLoB = sb + A_BYTES;
        uint32_t bHiB = sb + 2 * A_BYTES;
        uint32_t bLoB = bHiB + W_BYTES;

        #pragma unroll
        for (int ks = 0; ks < 2; ks++) {         // two k16 steps per chunk
            uint32_t aoff = (uint32_t)(wm + l15) * STRD + ks * 32 + lh16;
            uint32_t ahi[4][4], alo[4][4];
            #pragma unroll
            for (int mt = 0; mt < 4; mt++) {
                ldmat4(aHiB + aoff + mt * 16 * STRD, ahi[mt]);
                ldmat4(aLoB + aoff + mt * 16 * STRD, alo[mt]);
            }
            uint32_t boff = (uint32_t)(wn + brow) * STRD + ks * 32 + bk16;
            uint32_t bhi[4][2], blo[4][2];
            #pragma unroll
            for (int i = 0; i < 2; i++) {
                uint32_t r[4];
                ldmat4(bHiB + boff + i * 16 * STRD, r);
                bhi[2*i][0] = r[0]; bhi[2*i][1] = r[1];
                bhi[2*i+1][0] = r[2]; bhi[2*i+1][1] = r[3];
                ldmat4(bLoB + boff + i * 16 * STRD, r);
                blo[2*i][0] = r[0]; blo[2*i][1] = r[1];
                blo[2*i+1][0] = r[2]; blo[2*i+1][1] = r[3];
            }
            #pragma unroll
            for (int mt = 0; mt < 4; mt++)
                #pragma unroll
                for (int nt = 0; nt < 4; nt++) {
                    mma_bf16(acc[mt][nt], ahi[mt], bhi[nt]);
                    mma_bf16(acc[mt][nt], ahi[mt], blo[nt]);
                    mma_bf16(acc[mt][nt], alo[mt], bhi[nt]);
                }
        }
        __syncthreads();
        s ^= 1;
    }

    // Epilogue
    const int gid = lane >> 2, tig = lane & 3;
    #pragma unroll
    for (int mt = 0; mt < 4; mt++) {
        #pragma unroll
        for (int nt = 0; nt < 4; nt++) {
            int row = m0 + wm + mt * 16 + gid;
            int col = n0 + wn + nt * 8 + tig * 2;
            float v00 = acc[mt][nt][0] + bias[col];
            float v01 = acc[mt][nt][1] + bias[col + 1];
            float v10 = acc[mt][nt][2] + bias[col];
            float v11 = acc[mt][nt][3] + bias[col + 1];
            if (!scatter) {
                out[(size_t)row * CSZ + col]           = v00;
                out[(size_t)row * CSZ + col + 1]       = v01;
                out[(size_t)(row + 8) * CSZ + col]     = v10;
                out[(size_t)(row + 8) * CSZ + col + 1] = v11;
            } else {
                int b0 = row / TSZ, t0 = row % TSZ;
                int b1 = (row + 8) / TSZ, t1 = (row + 8) % TSZ;
                int h0 = col / HD, d0 = col % HD;
                int h1 = (col + 1) / HD, d1 = (col + 1) % HD;
                out[(((size_t)(b0 * NH + h0)) * TSZ + t0) * HD + d0] = v00;
                out[(((size_t)(b0 * NH + h1)) * TSZ + t0) * HD + d1] = v01;
                out[(((size_t)(b1 * NH + h0)) * TSZ + t1) * HD + d0] = v10;
                out[(((size_t)(b1 * NH + h1)) * TSZ + t1) * HD + d1] = v11;
            }
        }
    }
}

// ---------------------------------------------------------------------------
// RoPE, in place on g_q / g_k
// ---------------------------------------------------------------------------
__global__ void __launch_bounds__(256)
rope_kernel()
{
    const int total = BSZ * NH * TSZ * (HD / 2);
    int idx = blockIdx.x * blockDim.x + threadIdx.x;
    if (idx >= total) return;
    int i   = idx % (HD / 2);
    int row = idx / (HD / 2);
    int t   = row % TSZ;

    float inv_freq = expf(-((float)i / 24.0f) * 9.210340371976184f);
    float ang = (float)t * inv_freq;
    float s, c;
    sincosf(ang, &s, &c);

    float* q = g_q + row * HD;
    float* k = g_k + row * HD;
    float q1 = q[i], q2 = q[i + 24];
    q[i]      = q1 * c - q2 * s;
    q[i + 24] = q2 * c + q1 * s;
    float k1 = k[i], k2 = k[i + 24];
    k[i]      = k1 * c - k2 * s;
    k[i + 24] = k2 * c + k1 * s;
}

// ---------------------------------------------------------------------------
// Causal flash attention (fp32, 1 thread = 1 query row)
// ---------------------------------------------------------------------------
#define AQ 128
#define AK 64

__global__ void __launch_bounds__(128)
attn_kernel(const float* __restrict__ mask)
{
    __shared__ float4 Ks[AK * 12];
    __shared__ float4 Vs[AK * 12];
    __shared__ float  Ms[AK];

    const int bh = blockIdx.y;
    const int b  = bh >> 4;
    const int h  = bh & 15;
    const int qi = blockIdx.x * AQ + threadIdx.x;

    const float* qp = g_q + (bh * TSZ + qi) * HD;
    float4 q4[12];
    #pragma unroll
    for (int w = 0; w < 12; w++)
        q4[w] = *reinterpret_cast<const float4*>(qp + 4 * w);

    float4 o4[12];
    #pragma unroll
    for (int w = 0; w < 12; w++) o4[w] = make_float4(0.f, 0.f, 0.f, 0.f);

    float m = -1e30f, l = 0.f;
    const float scale = 0.14433756729740643f;

    const int ntile = (blockIdx.x + 1) * (AQ / AK);
    const float4* kbase = reinterpret_cast<const float4*>(g_k + bh * TSZ * HD);
    const float4* vbase = reinterpret_cast<const float4*>(g_v + bh * TSZ * HD);
    const float*  mrow  = mask + b * TSZ;

    for (int kt = 0; kt < ntile; kt++) {
        __syncthreads();
        const float4* ksrc = kbase + kt * AK * 12;
        const float4* vsrc = vbase + kt * AK * 12;
        for (int i = threadIdx.x; i < AK * 12; i += AQ) {
            Ks[i] = ksrc[i];
            Vs[i] = vsrc[i];
        }
        if (threadIdx.x < AK)
            Ms[threadIdx.x] = (1.0f - mrow[kt * AK + threadIdx.x]) * -10000.0f;
        __syncthreads();

        int jmax = qi - kt * AK + 1;
        if (jmax > AK) jmax = AK;

        for (int j = 0; j < jmax; j++) {
            const float4* kr = &Ks[j * 12];
            float s0 = 0.f, s1 = 0.f, s2 = 0.f, s3 = 0.f;
            #pragma unroll
            for (int w = 0; w < 12; w++) {
                float4 kv = kr[w];
                s0 += q4[w].x * kv.x;
                s1 += q4[w].y * kv.y;
                s2 += q4[w].z * kv.z;
                s3 += q4[w].w * kv.w;
            }
            float s = (s0 + s1) + (s2 + s3);
            s = s * scale + Ms[j];

            if (s > m) {
                float corr = __expf(m - s);
                m = s;
                l *= corr;
                #pragma unroll
                for (int w = 0; w < 12; w++) {
                    o4[w].x *= corr; o4[w].y *= corr;
                    o4[w].z *= corr; o4[w].w *= corr;
                }
            }
            float p = __expf(s - m);
            l += p;

            const float4* vr = &Vs[j * 12];
            #pragma unroll
            for (int w = 0; w < 12; w++) {
                float4 vv = vr[w];
                o4[w].x += p * vv.x; o4[w].y += p * vv.y;
                o4[w].z += p * vv.z; o4[w].w += p * vv.w;
            }
        }
    }

    const float inv_l = 1.0f / l;
    float* op = g_ctx + (b * TSZ + qi) * CSZ + h * HD;
    #pragma unroll
    for (int w = 0; w < 12; w++) {
        float4 r;
        r.x = o4[w].x * inv_l; r.y = o4[w].y * inv_l;
        r.z = o4[w].z * inv_l; r.w = o4[w].w * inv_l;
        *reinterpret_cast<float4*>(op + 4 * w) = r;
    }
}

// ---------------------------------------------------------------------------
extern "C" void kernel_launch(void* const* d_in, const int* in_sizes, int n_in,
                              void* d_out, int out_size)
{
    const float* X    = (const float*)d_in[0];
    const float* mask = (const float*)d_in[1];
    const float* Wq   = (const float*)d_in[2];
    const float* bq   = (const float*)d_in[3];
    const float* Wk   = (const float*)d_in[4];
    const float* bk   = (const float*)d_in[5];
    const float* Wv   = (const float*)d_in[6];
    const float* bv   = (const float*)d_in[7];
    const float* Wo   = (const float*)d_in[8];
    const float* bo   = (const float*)d_in[9];
    float* out = (float*)d_out;

    float *qb, *kb, *vb, *ctxb;
    cudaGetSymbolAddress((void**)&qb,   g_q);
    cudaGetSymbolAddress((void**)&kb,   g_k);
    cudaGetSymbolAddress((void**)&vb,   g_v);
    cudaGetSymbolAddress((void**)&ctxb, g_ctx);
    __nv_bfloat16 *xhi, *xlo, *chi, *clo, *whi, *wlo;
    cudaGetSymbolAddress((void**)&xhi, g_xhi);
    cudaGetSymbolAddress((void**)&xlo, g_xlo);
    cudaGetSymbolAddress((void**)&chi, g_chi);
    cudaGetSymbolAddress((void**)&clo, g_clo);
    cudaGetSymbolAddress((void**)&whi, g_whi);
    cudaGetSymbolAddress((void**)&wlo, g_wlo);

    cudaFuncSetAttribute(gemm_mma_kernel,
                         cudaFuncAttributeMaxDynamicSharedMemorySize, GEMM_SMEM);

    // Split-bf16 conversions
    int xn4 = MSZ * CSZ / 4;
    conv_kernel<<<(xn4 + 255) / 256, 256>>>(X, xhi, xlo, xn4);
    int wn4 = CSZ * CSZ / 4;
    conv_kernel<<<(wn4 + 255) / 256, 256>>>(Wq, whi + 0*CSZ*CSZ, wlo + 0*CSZ*CSZ, wn4);
    conv_kernel<<<(wn4 + 255) / 256, 256>>>(Wk, whi + 1*CSZ*CSZ, wlo + 1*CSZ*CSZ, wn4);
    conv_kernel<<<(wn4 + 255) / 256, 256>>>(Wv, whi + 2*CSZ*CSZ, wlo + 2*CSZ*CSZ, wn4);
    conv_kernel<<<(wn4 + 255) / 256, 256>>>(Wo, whi + 3*CSZ*CSZ, wlo + 3*CSZ*CSZ, wn4);

    // QKV projections (HMMA tensor cores) with head scatter
    dim3 ggrid(CSZ / CTA_N, MSZ / CTA_M);   // (12, 64)
    gemm_mma_kernel<<<ggrid, 128, GEMM_SMEM>>>(xhi, xlo, whi + 0*CSZ*CSZ, wlo + 0*CSZ*CSZ, bq, qb, 1);
    gemm_mma_kernel<<<ggrid, 128, GEMM_SMEM>>>(xhi, xlo, whi + 1*CSZ*CSZ, wlo + 1*CSZ*CSZ, bk, kb, 1);
    gemm_mma_kernel<<<ggrid, 128, GEMM_SMEM>>>(xhi, xlo, whi + 2*CSZ*CSZ, wlo + 2*CSZ*CSZ, bv, vb, 1);

    int rope_total = BSZ * NH * TSZ * (HD / 2);
    rope_kernel<<<(rope_total + 255) / 256, 256>>>();

    dim3 agrid(TSZ / AQ, BSZ * NH);   // (16, 64)
    attn_kernel<<<agrid, 128>>>(mask);

    // O projection
    conv_kernel<<<(xn4 + 255) / 256, 256>>>(ctxb, chi, clo, xn4);
    gemm_mma_kernel<<<ggrid, 128, GEMM_SMEM>>>(chi, clo, whi + 3*CSZ*CSZ, wlo + 3*CSZ*CSZ, bo, out, 0);
}

// round 5
// speedup vs baseline: 3.2155x; 2.0775x over previous
#include <cuda_runtime.h>
#include <cuda_bf16.h>
#include <cstdint>
#include <math.h>

#define BSZ 4
#define TSZ 2048
#define CSZ 768
#define NH  16
#define HD  48
#define MSZ (BSZ*TSZ)   // 8192
#define BH  (BSZ*NH)    // 64
#define L2E 1.4426950408889634f

// ---------------------------------------------------------------------------
// Scratch (device globals -> no allocation)
// ---------------------------------------------------------------------------
__device__ float g_q[BH*TSZ*HD];
__device__ float g_k[BH*TSZ*HD];
__device__ float g_v[BH*TSZ*HD];
__device__ float g_ctx[BSZ*TSZ*CSZ];

__device__ __nv_bfloat16 g_xhi[MSZ*CSZ];
__device__ __nv_bfloat16 g_xlo[MSZ*CSZ];
__device__ __nv_bfloat16 g_chi[MSZ*CSZ];
__device__ __nv_bfloat16 g_clo[MSZ*CSZ];
__device__ __nv_bfloat16 g_whi[4][CSZ*CSZ];
__device__ __nv_bfloat16 g_wlo[4][CSZ*CSZ];

// attention operands (bf16 hi/lo)
__device__ __nv_bfloat16 g_qhi[BH*TSZ*HD];
__device__ __nv_bfloat16 g_qlo[BH*TSZ*HD];
__device__ __nv_bfloat16 g_khi[BH*TSZ*HD];
__device__ __nv_bfloat16 g_klo[BH*TSZ*HD];
__device__ __nv_bfloat16 g_vthi[BH*HD*TSZ];   // transposed [bh][dv][t]
__device__ __nv_bfloat16 g_vtlo[BH*HD*TSZ];

// ---------------------------------------------------------------------------
// PTX helpers (compute_103-safe: mma.sync / ldmatrix / cp.async only)
// ---------------------------------------------------------------------------
__device__ __forceinline__ uint32_t smem_u32(const void* p) {
    uint32_t a;
    asm("{ .reg .u64 t; cvta.to.shared.u64 t, %1; cvt.u32.u64 %0, t; }"
        : "=r"(a) : "l"(p));
    return a;
}
__device__ __forceinline__ void cp_async16(uint32_t s, const void* g) {
    asm volatile("cp.async.ca.shared.global [%0], [%1], 16;" :: "r"(s), "l"(g));
}
#define CP_COMMIT() asm volatile("cp.async.commit_group;" ::: "memory")
#define CP_WAIT(n)  asm volatile("cp.async.wait_group %0;" :: "n"(n) : "memory")

__device__ __forceinline__ void ldmat4(uint32_t addr, uint32_t* r) {
    asm volatile("ldmatrix.sync.aligned.m8n8.x4.shared.b16 {%0,%1,%2,%3}, [%4];"
        : "=r"(r[0]), "=r"(r[1]), "=r"(r[2]), "=r"(r[3]) : "r"(addr));
}
__device__ __forceinline__ void mma_bf16(float* d, const uint32_t* a, const uint32_t* b) {
    asm volatile("mma.sync.aligned.m16n8k16.row.col.f32.bf16.bf16.f32 "
        "{%0,%1,%2,%3}, {%4,%5,%6,%7}, {%8,%9}, {%0,%1,%2,%3};"
        : "+f"(d[0]), "+f"(d[1]), "+f"(d[2]), "+f"(d[3])
        : "r"(a[0]), "r"(a[1]), "r"(a[2]), "r"(a[3]), "r"(b[0]), "r"(b[1]));
}

// FMA-pipe exp2 (no MUFU): t<=~1. floor + deg-6 poly + exponent-bit add.
__device__ __forceinline__ float fexp2(float t) {
    t = fmaxf(t, -126.0f);
    float fi = floorf(t);
    float f = t - fi;
    float p = 1.54035e-4f;
    p = fmaf(p, f, 1.33336e-3f);
    p = fmaf(p, f, 9.61813e-3f);
    p = fmaf(p, f, 5.55041e-2f);
    p = fmaf(p, f, 2.40227e-1f);
    p = fmaf(p, f, 6.93147e-1f);
    p = fmaf(p, f, 1.0f);
    int e = (int)fi;
    return __int_as_float(__float_as_int(p) + (e << 23));
}

// ---------------------------------------------------------------------------
// fp32 -> split bf16 (hi + lo)
// ---------------------------------------------------------------------------
__global__ void __launch_bounds__(256)
conv_kernel(const float* __restrict__ in, __nv_bfloat16* __restrict__ hi,
            __nv_bfloat16* __restrict__ lo, int n4)
{
    int i = blockIdx.x * blockDim.x + threadIdx.x;
    if (i >= n4) return;
    float4 x = reinterpret_cast<const float4*>(in)[i];
    __nv_bfloat16 h0 = __float2bfloat16(x.x);
    __nv_bfloat16 h1 = __float2bfloat16(x.y);
    __nv_bfloat16 h2 = __float2bfloat16(x.z);
    __nv_bfloat16 h3 = __float2bfloat16(x.w);
    __nv_bfloat162 hv0; hv0.x = h0; hv0.y = h1;
    __nv_bfloat162 hv1; hv1.x = h2; hv1.y = h3;
    __nv_bfloat162 lv0, lv1;
    lv0.x = __float2bfloat16(x.x - __bfloat162float(h0));
    lv0.y = __float2bfloat16(x.y - __bfloat162float(h1));
    lv1.x = __float2bfloat16(x.z - __bfloat162float(h2));
    lv1.y = __float2bfloat16(x.w - __bfloat162float(h3));
    reinterpret_cast<__nv_bfloat162*>(hi)[2*i]   = hv0;
    reinterpret_cast<__nv_bfloat162*>(hi)[2*i+1] = hv1;
    reinterpret_cast<__nv_bfloat162*>(lo)[2*i]   = lv0;
    reinterpret_cast<__nv_bfloat162*>(lo)[2*i+1] = lv1;
}

// ---------------------------------------------------------------------------
// mma.sync split-bf16 GEMM (unchanged from R3, validated)
// ---------------------------------------------------------------------------
#define CTA_M 128
#define CTA_N 64
#define KCH   32
#define NCH   (CSZ/KCH)        // 24
#define STRD  80
#define A_BYTES (CTA_M*STRD)
#define W_BYTES (CTA_N*STRD)
#define STAGE_BYTES (2*A_BYTES + 2*W_BYTES)
#define GEMM_SMEM (2*STAGE_BYTES)

__global__ void __launch_bounds__(128)
gemm_mma_kernel(const __nv_bfloat16* __restrict__ Ahi,
                const __nv_bfloat16* __restrict__ Alo,
                const __nv_bfloat16* __restrict__ Whi,
                const __nv_bfloat16* __restrict__ Wlo,
                const float* __restrict__ bias,
                float* __restrict__ out, int scatter)
{
    extern __shared__ char smem[];
    const int tid  = threadIdx.x;
    const int wid  = tid >> 5;
    const int lane = tid & 31;
    const int m0 = blockIdx.y * CTA_M;
    const int n0 = blockIdx.x * CTA_N;
    const int wm = (wid & 1) * 64;
    const int wn = (wid >> 1) * 32;
    const uint32_t sbase = smem_u32(smem);

    float acc[4][4][4];
    #pragma unroll
    for (int a = 0; a < 4; a++)
        #pragma unroll
        for (int b = 0; b < 4; b++)
            #pragma unroll
            for (int c = 0; c < 4; c++) acc[a][b][c] = 0.f;

    auto load_stage = [&](int kc, int s) {
        uint32_t sb = sbase + s * STAGE_BYTES;
        int kk = kc * KCH;
        #pragma unroll
        for (int i = 0; i < 8; i++) {
            int idx = i * 128 + tid;
            int part = idx >> 9, rem = idx & 511, row = rem >> 2, seg = rem & 3;
            const __nv_bfloat16* src =
                (part ? Alo : Ahi) + (size_t)(m0 + row) * CSZ + kk + seg * 8;
            cp_async16(sb + part * A_BYTES + row * STRD + seg * 16, src);
        }
        #pragma unroll
        for (int i = 0; i < 4; i++) {
            int idx = i * 128 + tid;
            int part = idx >> 8, rem = idx & 255, row = rem >> 2, seg = rem & 3;
            const __nv_bfloat16* src =
                (part ? Wlo : Whi) + (size_t)(n0 + row) * CSZ + kk + seg * 8;
            cp_async16(sb + 2 * A_BYTES + part * W_BYTES + row * STRD + seg * 16, src);
        }
        CP_COMMIT();
    };

    load_stage(0, 0);
    int s = 0;

    const int l15 = lane & 15;
    const int lh16 = (lane >> 4) * 16;
    const int brow = ((lane >> 4) << 3) + (lane & 7);
    const int bk16 = ((lane >> 3) & 1) * 16;

    for (int kc = 0; kc < NCH; kc++) {
        if (kc + 1 < NCH) { load_stage(kc + 1, s ^ 1); CP_WAIT(1); }
        else             { CP_WAIT(0); }
        __syncthreads();

        uint32_t sb   = sbase + s * STAGE_BYTES;
        uint32_t aHiB = sb;
        uint32_t aLoB = sb + A_BYTES;
        uint32_t bHiB = sb + 2 * A_BYTES;
        uint32_t bLoB = bHiB + W_BYTES;

        #pragma unroll
        for (int ks = 0; ks < 2; ks++) {
            uint32_t aoff = (uint32_t)(wm + l15) * STRD + ks * 32 + lh16;
            uint32_t ahi[4][4], alo[4][4];
            #pragma unroll
            for (int mt = 0; mt < 4; mt++) {
                ldmat4(aHiB + aoff + mt * 16 * STRD, ahi[mt]);
                ldmat4(aLoB + aoff + mt * 16 * STRD, alo[mt]);
            }
            uint32_t boff = (uint32_t)(wn + brow) * STRD + ks * 32 + bk16;
            uint32_t bhi[4][2], blo[4][2];
            #pragma unroll
            for (int i = 0; i < 2; i++) {
                uint32_t r[4];
                ldmat4(bHiB + boff + i * 16 * STRD, r);
                bhi[2*i][0] = r[0]; bhi[2*i][1] = r[1];
                bhi[2*i+1][0] = r[2]; bhi[2*i+1][1] = r[3];
                ldmat4(bLoB + boff + i * 16 * STRD, r);
                blo[2*i][0] = r[0]; blo[2*i][1] = r[1];
                blo[2*i+1][0] = r[2]; blo[2*i+1][1] = r[3];
            }
            #pragma unroll
            for (int mt = 0; mt < 4; mt++)
                #pragma unroll
                for (int nt = 0; nt < 4; nt++) {
                    mma_bf16(acc[mt][nt], ahi[mt], bhi[nt]);
                    mma_bf16(acc[mt][nt], ahi[mt], blo[nt]);
                    mma_bf16(acc[mt][nt], alo[mt], bhi[nt]);
                }
        }
        __syncthreads();
        s ^= 1;
    }

    const int gid = lane >> 2, tig = lane & 3;
    #pragma unroll
    for (int mt = 0; mt < 4; mt++) {
        #pragma unroll
        for (int nt = 0; nt < 4; nt++) {
            int row = m0 + wm + mt * 16 + gid;
            int col = n0 + wn + nt * 8 + tig * 2;
            float v00 = acc[mt][nt][0] + bias[col];
            float v01 = acc[mt][nt][1] + bias[col + 1];
            float v10 = acc[mt][nt][2] + bias[col];
            float v11 = acc[mt][nt][3] + bias[col + 1];
            if (!scatter) {
                out[(size_t)row * CSZ + col]           = v00;
                out[(size_t)row * CSZ + col + 1]       = v01;
                out[(size_t)(row + 8) * CSZ + col]     = v10;
                out[(size_t)(row + 8) * CSZ + col + 1] = v11;
            } else {
                int b0 = row / TSZ, t0 = row % TSZ;
                int b1 = (row + 8) / TSZ, t1 = (row + 8) % TSZ;
                int h0 = col / HD, d0 = col % HD;
                int h1 = (col + 1) / HD, d1 = (col + 1) % HD;
                out[(((size_t)(b0 * NH + h0)) * TSZ + t0) * HD + d0] = v00;
                out[(((size_t)(b0 * NH + h1)) * TSZ + t0) * HD + d1] = v01;
                out[(((size_t)(b1 * NH + h0)) * TSZ + t1) * HD + d0] = v10;
                out[(((size_t)(b1 * NH + h1)) * TSZ + t1) * HD + d1] = v11;
            }
        }
    }
}

// ---------------------------------------------------------------------------
// prep_qk: RoPE + scale(Q by 1/sqrt(48)) + split-bf16 Q/K. Consumes fp32 q/k.
// One thread per (row, i<24) rotation pair.
// ---------------------------------------------------------------------------
__global__ void __launch_bounds__(256)
prep_qk_kernel()
{
    const int total = BH * TSZ * (HD / 2);
    int idx = blockIdx.x * blockDim.x + threadIdx.x;
    if (idx >= total) return;
    int i   = idx % (HD / 2);
    int row = idx / (HD / 2);
    int t   = row % TSZ;

    float inv_freq = expf(-((float)i / 24.0f) * 9.210340371976184f);
    float ang = (float)t * inv_freq;
    float s, c;
    sincosf(ang, &s, &c);

    const float scale = 0.14433756729740643f;  // 1/sqrt(48)
    const float* q = g_q + (size_t)row * HD;
    const float* k = g_k + (size_t)row * HD;
    float q1 = q[i], q2 = q[i + 24];
    float k1 = k[i], k2 = k[i + 24];
    float qr1 = (q1 * c - q2 * s) * scale;
    float qr2 = (q2 * c + q1 * s) * scale;
    float kr1 = k1 * c - k2 * s;
    float kr2 = k2 * c + k1 * s;

    size_t o = (size_t)row * HD;
    __nv_bfloat16 h;
    h = __float2bfloat16(qr1); g_qhi[o+i] = h;    g_qlo[o+i]    = __float2bfloat16(qr1 - __bfloat162float(h));
    h = __float2bfloat16(qr2); g_qhi[o+i+24] = h; g_qlo[o+i+24] = __float2bfloat16(qr2 - __bfloat162float(h));
    h = __float2bfloat16(kr1); g_khi[o+i] = h;    g_klo[o+i]    = __float2bfloat16(kr1 - __bfloat162float(h));
    h = __float2bfloat16(kr2); g_khi[o+i+24] = h; g_klo[o+i+24] = __float2bfloat16(kr2 - __bfloat162float(h));
}

// ---------------------------------------------------------------------------
// prep_v: transpose V per head -> [bh][dv][t] with split-bf16, via smem tile.
// grid (T/64, BH), block 256.
// ---------------------------------------------------------------------------
__global__ void __launch_bounds__(256)
prep_v_kernel()
{
    __shared__ float sv[64][49];
    const int bh = blockIdx.y;
    const int t0 = blockIdx.x * 64;
    const int tid = threadIdx.x;

    const float* src = g_v + ((size_t)bh * TSZ + t0) * HD;
    for (int e = tid; e < 64 * HD; e += 256)
        sv[e / HD][e % HD] = src[e];
    __syncthreads();
    for (int e = tid; e < 64 * HD; e += 256) {
        int dv = e / 64, j = e % 64;
        float x = sv[j][dv];
        size_t o = ((size_t)bh * HD + dv) * TSZ + t0 + j;
        __nv_bfloat16 h = __float2bfloat16(x);
        g_vthi[o] = h;
        g_vtlo[o] = __float2bfloat16(x - __bfloat162float(h));
    }
}

// ---------------------------------------------------------------------------
// Tensor-core causal flash attention.
// CTA: 64 q rows, 4 warps x 16 rows. kv tiles of 64. Split-bf16 3-product
// for both S=QK^T and O=PV. FMA-pipe exp. Output -> g_ctx [B,T,C].
// ---------------------------------------------------------------------------
#define KSTRD 112          // 48 bf16 = 96B data + pad
#define VSTRD 144          // 64 bf16 = 128B data + pad

__global__ void __launch_bounds__(128)
attn_mma_kernel(const float* __restrict__ mask)
{
    __shared__ __align__(16) char sK[2][64 * KSTRD];
    __shared__ __align__(16) char sV[2][HD * VSTRD];
    __shared__ __align__(16) char sQ[2][64 * KSTRD];
    __shared__ float sMs[64];

    const int tid = threadIdx.x, wid = tid >> 5, lane = tid & 31;
    const int qt = gridDim.x - 1 - blockIdx.x;   // heavy CTAs first
    const int bh = blockIdx.y;
    const int b  = bh >> 4, h = bh & 15;
    const int q0 = qt * 64;

    const uint32_t uQh = smem_u32(sQ[0]), uQl = smem_u32(sQ[1]);
    const uint32_t uKh = smem_u32(sK[0]), uKl = smem_u32(sK[1]);
    const uint32_t uVh = smem_u32(sV[0]), uVl = smem_u32(sV[1]);

    // ---- load Q tile (once) ----
    {
        const __nv_bfloat16* qhg = g_qhi + ((size_t)bh * TSZ + q0) * HD;
        const __nv_bfloat16* qlg = g_qlo + ((size_t)bh * TSZ + q0) * HD;
        for (int i = tid; i < 384; i += 128) {
            int r = i / 6, s6 = i % 6;
            cp_async16(uQh + r * KSTRD + s6 * 16, qhg + r * HD + s6 * 8);
            cp_async16(uQl + r * KSTRD + s6 * 16, qlg + r * HD + s6 * 8);
        }
        CP_COMMIT(); CP_WAIT(0);
    }
    __syncthreads();

    // ---- extract Q fragments (kept in regs for whole kernel) ----
    const int l15 = lane & 15, lh16 = (lane >> 4) * 16;
    uint32_t qfh[3][4], qfl[3][4];
    #pragma unroll
    for (int k3 = 0; k3 < 3; k3++) {
        uint32_t off = (uint32_t)(wid * 16 + l15) * KSTRD + k3 * 32 + lh16;
        ldmat4(uQh + off, qfh[k3]);
        ldmat4(uQl + off, qfl[k3]);
    }

    float oacc[6][4];
    #pragma unroll
    for (int j = 0; j < 6; j++)
        #pragma unroll
        for (int c = 0; c < 4; c++) oacc[j][c] = 0.f;
    float m0 = -1e30f, m1 = -1e30f, l0 = 0.f, l1 = 0.f;

    const int brow = ((lane >> 4) << 3) + (lane & 7);
    const int bk16 = ((lane >> 3) & 1) * 16;
    const int gid = lane >> 2, tig = lane & 3;
    const int rbase0 = q0 + wid * 16 + gid;
    const int rbase1 = rbase0 + 8;
    const float* mrow = mask + b * TSZ;

    for (int kt = 0; kt <= qt; kt++) {
        __syncthreads();   // previous tile's smem reads done
        {
            const __nv_bfloat16* khg = g_khi + ((size_t)bh * TSZ + kt * 64) * HD;
            const __nv_bfloat16* klg = g_klo + ((size_t)bh * TSZ + kt * 64) * HD;
            for (int i = tid; i < 384; i += 128) {
                int r = i / 6, s6 = i % 6;
                cp_async16(uKh + r * KSTRD + s6 * 16, khg + r * HD + s6 * 8);
                cp_async16(uKl + r * KSTRD + s6 * 16, klg + r * HD + s6 * 8);
            }
            const __nv_bfloat16* vhg = g_vthi + (size_t)bh * HD * TSZ + kt * 64;
            const __nv_bfloat16* vlg = g_vtlo + (size_t)bh * HD * TSZ + kt * 64;
            for (int i = tid; i < 384; i += 128) {
                int r = i / 8, s8 = i % 8;
                cp_async16(uVh + r * VSTRD + s8 * 16, vhg + (size_t)r * TSZ + s8 * 8);
                cp_async16(uVl + r * VSTRD + s8 * 16, vlg + (size_t)r * TSZ + s8 * 8);
            }
            if (tid < 64) sMs[tid] = (1.0f - mrow[kt * 64 + tid]) * -10000.0f;
            CP_COMMIT(); CP_WAIT(0);
        }
        __syncthreads();

        // ---- S = Q K^T (scaled Q), 8 n-tiles of 8 kv cols ----
        float sa[8][4];
        #pragma unroll
        for (int j = 0; j < 8; j++)
            #pragma unroll
            for (int c = 0; c < 4; c++) sa[j][c] = 0.f;

        #pragma unroll
        for (int jp = 0; jp < 4; jp++) {
            #pragma unroll
            for (int k3 = 0; k3 < 3; k3++) {
                uint32_t koff = (uint32_t)(jp * 16 + brow) * KSTRD + k3 * 32 + bk16;
                uint32_t kh4[4], kl4[4];
                ldmat4(uKh + koff, kh4);
                ldmat4(uKl + koff, kl4);
                mma_bf16(sa[2*jp],   qfh[k3], kh4);     mma_bf16(sa[2*jp],   qfh[k3], kl4);
                mma_bf16(sa[2*jp],   qfl[k3], kh4);
                mma_bf16(sa[2*jp+1], qfh[k3], kh4+2);   mma_bf16(sa[2*jp+1], qfh[k3], kl4+2);
                mma_bf16(sa[2*jp+1], qfl[k3], kh4+2);
            }
        }

        // ---- mask + row stats ----
        const bool diag = (kt == qt);
        float mx0 = -1e30f, mx1 = -1e30f;
        #pragma unroll
        for (int j = 0; j < 8; j++) {
            int c0 = kt * 64 + 8 * j + 2 * tig;
            float ms0 = sMs[8*j + 2*tig], ms1 = sMs[8*j + 2*tig + 1];
            sa[j][0] += ms0; sa[j][1] += ms1; sa[j][2] += ms0; sa[j][3] += ms1;
            if (diag) {
                if (c0     > rbase0) sa[j][0] = -1e30f;
                if (c0 + 1 > rbase0) sa[j][1] = -1e30f;
                if (c0     > rbase1) sa[j][2] = -1e30f;
                if (c0 + 1 > rbase1) sa[j][3] = -1e30f;
            }
            mx0 = fmaxf(mx0, fmaxf(sa[j][0], sa[j][1]));
            mx1 = fmaxf(mx1, fmaxf(sa[j][2], sa[j][3]));
        }
        mx0 = fmaxf(mx0, __shfl_xor_sync(0xffffffffu, mx0, 1));
        mx0 = fmaxf(mx0, __shfl_xor_sync(0xffffffffu, mx0, 2));
        mx1 = fmaxf(mx1, __shfl_xor_sync(0xffffffffu, mx1, 1));
        mx1 = fmaxf(mx1, __shfl_xor_sync(0xffffffffu, mx1, 2));
        float mn0 = fmaxf(m0, mx0), mn1 = fmaxf(m1, mx1);
        float cr0 = fexp2((m0 - mn0) * L2E);
        float cr1 = fexp2((m1 - mn1) * L2E);
        m0 = mn0; m1 = mn1;

        // ---- exp + P fragments (bf16 hi/lo) ----
        float su0 = 0.f, su1 = 0.f;
        uint32_t pah[4][4], pal[4][4];
        #pragma unroll
        for (int j = 0; j < 8; j++) {
            float p0 = fexp2((sa[j][0] - mn0) * L2E);
            float p1 = fexp2((sa[j][1] - mn0) * L2E);
            float p2 = fexp2((sa[j][2] - mn1) * L2E);
            float p3 = fexp2((sa[j][3] - mn1) * L2E);
            su0 += p0 + p1; su1 += p2 + p3;
            __nv_bfloat162 h01, h23, lo01, lo23;
            h01.x = __float2bfloat16(p0); h01.y = __float2bfloat16(p1);
            h23.x = __float2bfloat16(p2); h23.y = __float2bfloat16(p3);
            lo01.x = __float2bfloat16(p0 - __bfloat162float(h01.x));
            lo01.y = __float2bfloat16(p1 - __bfloat162float(h01.y));
            lo23.x = __float2bfloat16(p2 - __bfloat162float(h23.x));
            lo23.y = __float2bfloat16(p3 - __bfloat162float(h23.y));
            int t = j >> 1, hf = j & 1;
            pah[t][hf*2]   = *reinterpret_cast<uint32_t*>(&h01);
            pah[t][hf*2+1] = *reinterpret_cast<uint32_t*>(&h23);
            pal[t][hf*2]   = *reinterpret_cast<uint32_t*>(&lo01);
            pal[t][hf*2+1] = *reinterpret_cast<uint32_t*>(&lo23);
        }
        su0 += __shfl_xor_sync(0xffffffffu, su0, 1);
        su0 += __shfl_xor_sync(0xffffffffu, su0, 2);
        su1 += __shfl_xor_sync(0xffffffffu, su1, 1);
        su1 += __shfl_xor_sync(0xffffffffu, su1, 2);
        l0 = l0 * cr0 + su0;
        l1 = l1 * cr1 + su1;
        #pragma unroll
        for (int j = 0; j < 6; j++) {
            oacc[j][0] *= cr0; oacc[j][1] *= cr0;
            oacc[j][2] *= cr1; oacc[j][3] *= cr1;
        }

        // ---- O += P V ----
        #pragma unroll
        for (int np = 0; np < 3; np++) {
            #pragma unroll
            for (int t = 0; t < 4; t++) {
                uint32_t voff = (uint32_t)(np * 16 + brow) * VSTRD + t * 32 + bk16;
                uint32_t vh4[4], vl4[4];
                ldmat4(uVh + voff, vh4);
                ldmat4(uVl + voff, vl4);
                mma_bf16(oacc[2*np],   pah[t], vh4);     mma_bf16(oacc[2*np],   pah[t], vl4);
                mma_bf16(oacc[2*np],   pal[t], vh4);
                mma_bf16(oacc[2*np+1], pah[t], vh4+2);   mma_bf16(oacc[2*np+1], pah[t], vl4+2);
                mma_bf16(oacc[2*np+1], pal[t], vh4+2);
            }
        }
    }

    // ---- epilogue ----
    float il0 = 1.0f / l0, il1 = 1.0f / l1;
    float* o0 = g_ctx + ((size_t)b * TSZ + rbase0) * CSZ + h * HD;
    float* o1 = g_ctx + ((size_t)b * TSZ + rbase1) * CSZ + h * HD;
    #pragma unroll
    for (int j = 0; j < 6; j++) {
        int dv = 8 * j + 2 * tig;
        float2 r0 = make_float2(oacc[j][0] * il0, oacc[j][1] * il0);
        float2 r1 = make_float2(oacc[j][2] * il1, oacc[j][3] * il1);
        *reinterpret_cast<float2*>(o0 + dv) = r0;
        *reinterpret_cast<float2*>(o1 + dv) = r1;
    }
}

// ---------------------------------------------------------------------------
extern "C" void kernel_launch(void* const* d_in, const int* in_sizes, int n_in,
                              void* d_out, int out_size)
{
    const float* X    = (const float*)d_in[0];
    const float* mask = (const float*)d_in[1];
    const float* Wq   = (const float*)d_in[2];
    const float* bq   = (const float*)d_in[3];
    const float* Wk   = (const float*)d_in[4];
    const float* bk   = (const float*)d_in[5];
    const float* Wv   = (const float*)d_in[6];
    const float* bv   = (const float*)d_in[7];
    const float* Wo   = (const float*)d_in[8];
    const float* bo   = (const float*)d_in[9];
    float* out = (float*)d_out;

    float *qb, *kb, *vb, *ctxb;
    cudaGetSymbolAddress((void**)&qb,   g_q);
    cudaGetSymbolAddress((void**)&kb,   g_k);
    cudaGetSymbolAddress((void**)&vb,   g_v);
    cudaGetSymbolAddress((void**)&ctxb, g_ctx);
    __nv_bfloat16 *xhi, *xlo, *chi, *clo, *whi, *wlo;
    cudaGetSymbolAddress((void**)&xhi, g_xhi);
    cudaGetSymbolAddress((void**)&xlo, g_xlo);
    cudaGetSymbolAddress((void**)&chi, g_chi);
    cudaGetSymbolAddress((void**)&clo, g_clo);
    cudaGetSymbolAddress((void**)&whi, g_whi);
    cudaGetSymbolAddress((void**)&wlo, g_wlo);

    cudaFuncSetAttribute(gemm_mma_kernel,
                         cudaFuncAttributeMaxDynamicSharedMemorySize, GEMM_SMEM);

    // Split-bf16 conversions
    int xn4 = MSZ * CSZ / 4;
    conv_kernel<<<(xn4 + 255) / 256, 256>>>(X, xhi, xlo, xn4);
    int wn4 = CSZ * CSZ / 4;
    conv_kernel<<<(wn4 + 255) / 256, 256>>>(Wq, whi + 0*CSZ*CSZ, wlo + 0*CSZ*CSZ, wn4);
    conv_kernel<<<(wn4 + 255) / 256, 256>>>(Wk, whi + 1*CSZ*CSZ, wlo + 1*CSZ*CSZ, wn4);
    conv_kernel<<<(wn4 + 255) / 256, 256>>>(Wv, whi + 2*CSZ*CSZ, wlo + 2*CSZ*CSZ, wn4);
    conv_kernel<<<(wn4 + 255) / 256, 256>>>(Wo, whi + 3*CSZ*CSZ, wlo + 3*CSZ*CSZ, wn4);

    // QKV projections (HMMA) with head scatter -> fp32 q/k/v
    dim3 ggrid(CSZ / CTA_N, MSZ / CTA_M);   // (12, 64)
    gemm_mma_kernel<<<ggrid, 128, GEMM_SMEM>>>(xhi, xlo, whi + 0*CSZ*CSZ, wlo + 0*CSZ*CSZ, bq, qb, 1);
    gemm_mma_kernel<<<ggrid, 128, GEMM_SMEM>>>(xhi, xlo, whi + 1*CSZ*CSZ, wlo + 1*CSZ*CSZ, bk, kb, 1);
    gemm_mma_kernel<<<ggrid, 128, GEMM_SMEM>>>(xhi, xlo, whi + 2*CSZ*CSZ, wlo + 2*CSZ*CSZ, bv, vb, 1);

    // RoPE + scale + split-bf16 (Q/K), transpose + split (V)
    int pq_total = BH * TSZ * (HD / 2);
    prep_qk_kernel<<<(pq_total + 255) / 256, 256>>>();
    dim3 pvgrid(TSZ / 64, BH);
    prep_v_kernel<<<pvgrid, 256>>>();

    // Tensor-core flash attention
    dim3 agrid(TSZ / 64, BH);   // (32, 64)
    attn_mma_kernel<<<agrid, 128>>>(mask);

    // O projection
    conv_kernel<<<(xn4 + 255) / 256, 256>>>(ctxb, chi, clo, xn4);
    gemm_mma_kernel<<<ggrid, 128, GEMM_SMEM>>>(chi, clo, whi + 3*CSZ*CSZ, wlo + 3*CSZ*CSZ, bo, out, 0);
}

// round 6
// speedup vs baseline: 3.2252x; 1.0030x over previous
#include <cuda_runtime.h>
#include <cuda_bf16.h>
#include <cstdint>
#include <math.h>

#define BSZ 4
#define TSZ 2048
#define CSZ 768
#define NH  16
#define HD  48
#define MSZ (BSZ*TSZ)   // 8192
#define BH  (BSZ*NH)    // 64
#define L2E 1.4426950408889634f

// ---------------------------------------------------------------------------
// Scratch (device globals -> no allocation)
// ---------------------------------------------------------------------------
__device__ float g_q[BH*TSZ*HD];
__device__ float g_k[BH*TSZ*HD];
__device__ float g_v[BH*TSZ*HD];

__device__ __nv_bfloat16 g_xhi[MSZ*CSZ];
__device__ __nv_bfloat16 g_xlo[MSZ*CSZ];
__device__ __nv_bfloat16 g_chi[MSZ*CSZ];
__device__ __nv_bfloat16 g_clo[MSZ*CSZ];
__device__ __nv_bfloat16 g_whi[4][CSZ*CSZ];
__device__ __nv_bfloat16 g_wlo[4][CSZ*CSZ];

// attention operands (bf16 hi/lo)
__device__ __nv_bfloat16 g_qhi[BH*TSZ*HD];
__device__ __nv_bfloat16 g_qlo[BH*TSZ*HD];
__device__ __nv_bfloat16 g_khi[BH*TSZ*HD];
__device__ __nv_bfloat16 g_klo[BH*TSZ*HD];
__device__ __nv_bfloat16 g_vthi[BH*HD*TSZ];   // transposed [bh][dv][t]
__device__ __nv_bfloat16 g_vtlo[BH*HD*TSZ];

// ---------------------------------------------------------------------------
// PTX helpers (compute_103-safe: mma.sync / ldmatrix / cp.async only)
// ---------------------------------------------------------------------------
__device__ __forceinline__ uint32_t smem_u32(const void* p) {
    uint32_t a;
    asm("{ .reg .u64 t; cvta.to.shared.u64 t, %1; cvt.u32.u64 %0, t; }"
        : "=r"(a) : "l"(p));
    return a;
}
__device__ __forceinline__ void cp_async16(uint32_t s, const void* g) {
    asm volatile("cp.async.ca.shared.global [%0], [%1], 16;" :: "r"(s), "l"(g));
}
#define CP_COMMIT() asm volatile("cp.async.commit_group;" ::: "memory")
#define CP_WAIT(n)  asm volatile("cp.async.wait_group %0;" :: "n"(n) : "memory")

__device__ __forceinline__ void ldmat4(uint32_t addr, uint32_t* r) {
    asm volatile("ldmatrix.sync.aligned.m8n8.x4.shared.b16 {%0,%1,%2,%3}, [%4];"
        : "=r"(r[0]), "=r"(r[1]), "=r"(r[2]), "=r"(r[3]) : "r"(addr));
}
__device__ __forceinline__ void mma_bf16(float* d, const uint32_t* a, const uint32_t* b) {
    asm volatile("mma.sync.aligned.m16n8k16.row.col.f32.bf16.bf16.f32 "
        "{%0,%1,%2,%3}, {%4,%5,%6,%7}, {%8,%9}, {%0,%1,%2,%3};"
        : "+f"(d[0]), "+f"(d[1]), "+f"(d[2]), "+f"(d[3])
        : "r"(a[0]), "r"(a[1]), "r"(a[2]), "r"(a[3]), "r"(b[0]), "r"(b[1]));
}

// FMA-pipe exp2 (no MUFU)
__device__ __forceinline__ float fexp2(float t) {
    t = fmaxf(t, -126.0f);
    float fi = floorf(t);
    float f = t - fi;
    float p = 1.54035e-4f;
    p = fmaf(p, f, 1.33336e-3f);
    p = fmaf(p, f, 9.61813e-3f);
    p = fmaf(p, f, 5.55041e-2f);
    p = fmaf(p, f, 2.40227e-1f);
    p = fmaf(p, f, 6.93147e-1f);
    p = fmaf(p, f, 1.0f);
    int e = (int)fi;
    return __int_as_float(__float_as_int(p) + (e << 23));
}

// ---------------------------------------------------------------------------
// fp32 -> split bf16 (hi + lo)
// ---------------------------------------------------------------------------
__global__ void __launch_bounds__(256)
conv_kernel(const float* __restrict__ in, __nv_bfloat16* __restrict__ hi,
            __nv_bfloat16* __restrict__ lo, int n4)
{
    int i = blockIdx.x * blockDim.x + threadIdx.x;
    if (i >= n4) return;
    float4 x = reinterpret_cast<const float4*>(in)[i];
    __nv_bfloat16 h0 = __float2bfloat16(x.x);
    __nv_bfloat16 h1 = __float2bfloat16(x.y);
    __nv_bfloat16 h2 = __float2bfloat16(x.z);
    __nv_bfloat16 h3 = __float2bfloat16(x.w);
    __nv_bfloat162 hv0; hv0.x = h0; hv0.y = h1;
    __nv_bfloat162 hv1; hv1.x = h2; hv1.y = h3;
    __nv_bfloat162 lv0, lv1;
    lv0.x = __float2bfloat16(x.x - __bfloat162float(h0));
    lv0.y = __float2bfloat16(x.y - __bfloat162float(h1));
    lv1.x = __float2bfloat16(x.z - __bfloat162float(h2));
    lv1.y = __float2bfloat16(x.w - __bfloat162float(h3));
    reinterpret_cast<__nv_bfloat162*>(hi)[2*i]   = hv0;
    reinterpret_cast<__nv_bfloat162*>(hi)[2*i+1] = hv1;
    reinterpret_cast<__nv_bfloat162*>(lo)[2*i]   = lv0;
    reinterpret_cast<__nv_bfloat162*>(lo)[2*i+1] = lv1;
}

// ---------------------------------------------------------------------------
// mma.sync split-bf16 GEMM: 256 threads, CTA 128x128, 8 warps of 64x32.
// out[m,n] = sum_k A[m,k]*W[n,k] + bias[n]; D = AhiWhi + AhiWlo + AloWhi.
// ---------------------------------------------------------------------------
#define CTA_M 128
#define CTA_N 128
#define KCH   32
#define NCH   (CSZ/KCH)        // 24
#define STRD  80
#define A_BYTES (CTA_M*STRD)   // 10240
#define W_BYTES (CTA_N*STRD)   // 10240
#define STAGE_BYTES (2*A_BYTES + 2*W_BYTES)  // 40960
#define GEMM_SMEM (2*STAGE_BYTES)            // 81920

__global__ void __launch_bounds__(256)
gemm_mma_kernel(const __nv_bfloat16* __restrict__ Ahi,
                const __nv_bfloat16* __restrict__ Alo,
                const __nv_bfloat16* __restrict__ Whi,
                const __nv_bfloat16* __restrict__ Wlo,
                const float* __restrict__ bias,
                float* __restrict__ out, int scatter)
{
    extern __shared__ char smem[];
    const int tid  = threadIdx.x;
    const int wid  = tid >> 5;
    const int lane = tid & 31;
    const int m0 = blockIdx.y * CTA_M;
    const int n0 = blockIdx.x * CTA_N;
    const int wm = (wid & 1) * 64;          // {0,64}
    const int wn = (wid >> 1) * 32;         // {0,32,64,96}
    const uint32_t sbase = smem_u32(smem);

    float acc[4][4][4];
    #pragma unroll
    for (int a = 0; a < 4; a++)
        #pragma unroll
        for (int b = 0; b < 4; b++)
            #pragma unroll
            for (int c = 0; c < 4; c++) acc[a][b][c] = 0.f;

    auto load_stage = [&](int kc, int s) {
        uint32_t sb = sbase + s * STAGE_BYTES;
        int kk = kc * KCH;
        #pragma unroll
        for (int i = 0; i < 4; i++) {            // A hi+lo: 1024 x 16B
            int idx = i * 256 + tid;
            int part = idx >> 9, rem = idx & 511, row = rem >> 2, seg = rem & 3;
            const __nv_bfloat16* src =
                (part ? Alo : Ahi) + (size_t)(m0 + row) * CSZ + kk + seg * 8;
            cp_async16(sb + part * A_BYTES + row * STRD + seg * 16, src);
        }
        #pragma unroll
        for (int i = 0; i < 4; i++) {            // W hi+lo: 1024 x 16B
            int idx = i * 256 + tid;
            int part = idx >> 9, rem = idx & 511, row = rem >> 2, seg = rem & 3;
            const __nv_bfloat16* src =
                (part ? Wlo : Whi) + (size_t)(n0 + row) * CSZ + kk + seg * 8;
            cp_async16(sb + 2 * A_BYTES + part * W_BYTES + row * STRD + seg * 16, src);
        }
        CP_COMMIT();
    };

    load_stage(0, 0);
    int s = 0;

    const int l15 = lane & 15;
    const int lh16 = (lane >> 4) * 16;
    const int brow = ((lane >> 4) << 3) + (lane & 7);
    const int bk16 = ((lane >> 3) & 1) * 16;

    for (int kc = 0; kc < NCH; kc++) {
        if (kc + 1 < NCH) { load_stage(kc + 1, s ^ 1); CP_WAIT(1); }
        else             { CP_WAIT(0); }
        __syncthreads();

        uint32_t sb   = sbase + s * STAGE_BYTES;
        uint32_t aHiB = sb;
        uint32_t aLoB = sb + A_BYTES;
        uint32_t bHiB = sb + 2 * A_BYTES;
        uint32_t bLoB = bHiB + W_BYTES;

        #pragma unroll
        for (int ks = 0; ks < 2; ks++) {
            uint32_t aoff = (uint32_t)(wm + l15) * STRD + ks * 32 + lh16;
            uint32_t ahi[4][4], alo[4][4];
            #pragma unroll
            for (int mt = 0; mt < 4; mt++) {
                ldmat4(aHiB + aoff + mt * 16 * STRD, ahi[mt]);
                ldmat4(aLoB + aoff + mt * 16 * STRD, alo[mt]);
            }
            uint32_t boff = (uint32_t)(wn + brow) * STRD + ks * 32 + bk16;
            uint32_t bhi[4][2], blo[4][2];
            #pragma unroll
            for (int i = 0; i < 2; i++) {
                uint32_t r[4];
                ldmat4(bHiB + boff + i * 16 * STRD, r);
                bhi[2*i][0] = r[0]; bhi[2*i][1] = r[1];
                bhi[2*i+1][0] = r[2]; bhi[2*i+1][1] = r[3];
                ldmat4(bLoB + boff + i * 16 * STRD, r);
                blo[2*i][0] = r[0]; blo[2*i][1] = r[1];
                blo[2*i+1][0] = r[2]; blo[2*i+1][1] = r[3];
            }
            #pragma unroll
            for (int mt = 0; mt < 4; mt++)
                #pragma unroll
                for (int nt = 0; nt < 4; nt++) {
                    mma_bf16(acc[mt][nt], ahi[mt], bhi[nt]);
                    mma_bf16(acc[mt][nt], ahi[mt], blo[nt]);
                    mma_bf16(acc[mt][nt], alo[mt], bhi[nt]);
                }
        }
        __syncthreads();
        s ^= 1;
    }

    const int gid = lane >> 2, tig = lane & 3;
    #pragma unroll
    for (int mt = 0; mt < 4; mt++) {
        #pragma unroll
        for (int nt = 0; nt < 4; nt++) {
            int row = m0 + wm + mt * 16 + gid;
            int col = n0 + wn + nt * 8 + tig * 2;
            float v00 = acc[mt][nt][0] + bias[col];
            float v01 = acc[mt][nt][1] + bias[col + 1];
            float v10 = acc[mt][nt][2] + bias[col];
            float v11 = acc[mt][nt][3] + bias[col + 1];
            if (!scatter) {
                out[(size_t)row * CSZ + col]           = v00;
                out[(size_t)row * CSZ + col + 1]       = v01;
                out[(size_t)(row + 8) * CSZ + col]     = v10;
                out[(size_t)(row + 8) * CSZ + col + 1] = v11;
            } else {
                int b0 = row / TSZ, t0 = row % TSZ;
                int b1 = (row + 8) / TSZ, t1 = (row + 8) % TSZ;
                int h0 = col / HD, d0 = col % HD;
                int h1 = (col + 1) / HD, d1 = (col + 1) % HD;
                out[(((size_t)(b0 * NH + h0)) * TSZ + t0) * HD + d0] = v00;
                out[(((size_t)(b0 * NH + h1)) * TSZ + t0) * HD + d1] = v01;
                out[(((size_t)(b1 * NH + h0)) * TSZ + t1) * HD + d0] = v10;
                out[(((size_t)(b1 * NH + h1)) * TSZ + t1) * HD + d1] = v11;
            }
        }
    }
}

// ---------------------------------------------------------------------------
// prep_qk: RoPE + scale(Q) + split-bf16 Q/K
// ---------------------------------------------------------------------------
__global__ void __launch_bounds__(256)
prep_qk_kernel()
{
    const int total = BH * TSZ * (HD / 2);
    int idx = blockIdx.x * blockDim.x + threadIdx.x;
    if (idx >= total) return;
    int i   = idx % (HD / 2);
    int row = idx / (HD / 2);
    int t   = row % TSZ;

    float inv_freq = expf(-((float)i / 24.0f) * 9.210340371976184f);
    float ang = (float)t * inv_freq;
    float s, c;
    sincosf(ang, &s, &c);

    const float scale = 0.14433756729740643f;
    const float* q = g_q + (size_t)row * HD;
    const float* k = g_k + (size_t)row * HD;
    float q1 = q[i], q2 = q[i + 24];
    float k1 = k[i], k2 = k[i + 24];
    float qr1 = (q1 * c - q2 * s) * scale;
    float qr2 = (q2 * c + q1 * s) * scale;
    float kr1 = k1 * c - k2 * s;
    float kr2 = k2 * c + k1 * s;

    size_t o = (size_t)row * HD;
    __nv_bfloat16 h;
    h = __float2bfloat16(qr1); g_qhi[o+i] = h;    g_qlo[o+i]    = __float2bfloat16(qr1 - __bfloat162float(h));
    h = __float2bfloat16(qr2); g_qhi[o+i+24] = h; g_qlo[o+i+24] = __float2bfloat16(qr2 - __bfloat162float(h));
    h = __float2bfloat16(kr1); g_khi[o+i] = h;    g_klo[o+i]    = __float2bfloat16(kr1 - __bfloat162float(h));
    h = __float2bfloat16(kr2); g_khi[o+i+24] = h; g_klo[o+i+24] = __float2bfloat16(kr2 - __bfloat162float(h));
}

// ---------------------------------------------------------------------------
// prep_v: transpose V per head -> [bh][dv][t] split-bf16
// ---------------------------------------------------------------------------
__global__ void __launch_bounds__(256)
prep_v_kernel()
{
    __shared__ float sv[64][49];
    const int bh = blockIdx.y;
    const int t0 = blockIdx.x * 64;
    const int tid = threadIdx.x;

    const float* src = g_v + ((size_t)bh * TSZ + t0) * HD;
    for (int e = tid; e < 64 * HD; e += 256)
        sv[e / HD][e % HD] = src[e];
    __syncthreads();
    for (int e = tid; e < 64 * HD; e += 256) {
        int dv = e / 64, j = e % 64;
        float x = sv[j][dv];
        size_t o = ((size_t)bh * HD + dv) * TSZ + t0 + j;
        __nv_bfloat16 h = __float2bfloat16(x);
        g_vthi[o] = h;
        g_vtlo[o] = __float2bfloat16(x - __bfloat162float(h));
    }
}

// ---------------------------------------------------------------------------
// Tensor-core causal flash attention, double-buffered K/V, bf16 hi/lo output.
// ---------------------------------------------------------------------------
#define KSTRD 112          // 48 bf16 = 96B data + pad
#define VSTRD 144          // 64 bf16 = 128B data + pad
#define QTB   (64*KSTRD)   // 7168
#define KTB   (64*KSTRD)   // 7168
#define VTB   (HD*VSTRD)   // 6912
// dynamic smem layout
#define O_QH  0
#define O_QL  (O_QH + QTB)
#define O_KV(s)  (O_QL + QTB + (s) * (2*KTB + 2*VTB))
#define O_MS(s)  (O_QL + QTB + 2*(2*KTB + 2*VTB) + (s) * 256)
#define ATTN_SMEM (O_QL + QTB + 2*(2*KTB + 2*VTB) + 512)  // 71168

__global__ void __launch_bounds__(128)
attn_mma_kernel(const float* __restrict__ mask)
{
    extern __shared__ char asm_[];
    const uint32_t sbase = smem_u32(asm_);
    float* sMs[2] = { (float*)(asm_ + O_MS(0)), (float*)(asm_ + O_MS(1)) };

    const int tid = threadIdx.x, wid = tid >> 5, lane = tid & 31;
    const int qt = gridDim.x - 1 - blockIdx.x;   // heavy CTAs first
    const int bh = blockIdx.y;
    const int b  = bh >> 4, h = bh & 15;
    const int q0 = qt * 64;

    const uint32_t uQh = sbase + O_QH, uQl = sbase + O_QL;
    const float* mrow = mask + b * TSZ;

    // ---- load Q tile (once) ----
    {
        const __nv_bfloat16* qhg = g_qhi + ((size_t)bh * TSZ + q0) * HD;
        const __nv_bfloat16* qlg = g_qlo + ((size_t)bh * TSZ + q0) * HD;
        for (int i = tid; i < 384; i += 128) {
            int r = i / 6, s6 = i % 6;
            cp_async16(uQh + r * KSTRD + s6 * 16, qhg + r * HD + s6 * 8);
            cp_async16(uQl + r * KSTRD + s6 * 16, qlg + r * HD + s6 * 8);
        }
        CP_COMMIT(); CP_WAIT(0);
    }
    __syncthreads();

    // ---- Q fragments in regs ----
    const int l15 = lane & 15, lh16 = (lane >> 4) * 16;
    uint32_t qfh[3][4], qfl[3][4];
    #pragma unroll
    for (int k3 = 0; k3 < 3; k3++) {
        uint32_t off = (uint32_t)(wid * 16 + l15) * KSTRD + k3 * 32 + lh16;
        ldmat4(uQh + off, qfh[k3]);
        ldmat4(uQl + off, qfl[k3]);
    }

    auto load_kv = [&](int kt, int s) {
        uint32_t base = sbase + O_KV(s);
        uint32_t kh = base, kl = base + KTB, vh = base + 2*KTB, vl = base + 2*KTB + VTB;
        const __nv_bfloat16* khg = g_khi + ((size_t)bh * TSZ + kt * 64) * HD;
        const __nv_bfloat16* klg = g_klo + ((size_t)bh * TSZ + kt * 64) * HD;
        for (int i = tid; i < 384; i += 128) {
            int r = i / 6, s6 = i % 6;
            cp_async16(kh + r * KSTRD + s6 * 16, khg + r * HD + s6 * 8);
            cp_async16(kl + r * KSTRD + s6 * 16, klg + r * HD + s6 * 8);
        }
        const __nv_bfloat16* vhg = g_vthi + (size_t)bh * HD * TSZ + kt * 64;
        const __nv_bfloat16* vlg = g_vtlo + (size_t)bh * HD * TSZ + kt * 64;
        for (int i = tid; i < 384; i += 128) {
            int r = i / 8, s8 = i % 8;
            cp_async16(vh + r * VSTRD + s8 * 16, vhg + (size_t)r * TSZ + s8 * 8);
            cp_async16(vl + r * VSTRD + s8 * 16, vlg + (size_t)r * TSZ + s8 * 8);
        }
        if (tid < 64) sMs[s][tid] = (1.0f - mrow[kt * 64 + tid]) * -10000.0f;
        CP_COMMIT();
    };

    float oacc[6][4];
    #pragma unroll
    for (int j = 0; j < 6; j++)
        #pragma unroll
        for (int c = 0; c < 4; c++) oacc[j][c] = 0.f;
    float m0 = -1e30f, m1 = -1e30f, l0 = 0.f, l1 = 0.f;

    const int brow = ((lane >> 4) << 3) + (lane & 7);
    const int bk16 = ((lane >> 3) & 1) * 16;
    const int gid = lane >> 2, tig = lane & 3;
    const int rbase0 = q0 + wid * 16 + gid;
    const int rbase1 = rbase0 + 8;

    load_kv(0, 0);
    int st = 0;

    for (int kt = 0; kt <= qt; kt++) {
        if (kt < qt) { load_kv(kt + 1, st ^ 1); CP_WAIT(1); }
        else         { CP_WAIT(0); }
        __syncthreads();

        uint32_t base = sbase + O_KV(st);
        uint32_t uKh = base, uKl = base + KTB;
        uint32_t uVh = base + 2*KTB, uVl = base + 2*KTB + VTB;
        float* ms = sMs[st];

        // ---- S = Q K^T ----
        float sa[8][4];
        #pragma unroll
        for (int j = 0; j < 8; j++)
            #pragma unroll
            for (int c = 0; c < 4; c++) sa[j][c] = 0.f;

        #pragma unroll
        for (int jp = 0; jp < 4; jp++) {
            #pragma unroll
            for (int k3 = 0; k3 < 3; k3++) {
                uint32_t koff = (uint32_t)(jp * 16 + brow) * KSTRD + k3 * 32 + bk16;
                uint32_t kh4[4], kl4[4];
                ldmat4(uKh + koff, kh4);
                ldmat4(uKl + koff, kl4);
                mma_bf16(sa[2*jp],   qfh[k3], kh4);     mma_bf16(sa[2*jp],   qfh[k3], kl4);
                mma_bf16(sa[2*jp],   qfl[k3], kh4);
                mma_bf16(sa[2*jp+1], qfh[k3], kh4+2);   mma_bf16(sa[2*jp+1], qfh[k3], kl4+2);
                mma_bf16(sa[2*jp+1], qfl[k3], kh4+2);
            }
        }

        // ---- mask + row stats ----
        const bool diag = (kt == qt);
        float mx0 = -1e30f, mx1 = -1e30f;
        #pragma unroll
        for (int j = 0; j < 8; j++) {
            int c0 = kt * 64 + 8 * j + 2 * tig;
            float ms0 = ms[8*j + 2*tig], ms1 = ms[8*j + 2*tig + 1];
            sa[j][0] += ms0; sa[j][1] += ms1; sa[j][2] += ms0; sa[j][3] += ms1;
            if (diag) {
                if (c0     > rbase0) sa[j][0] = -1e30f;
                if (c0 + 1 > rbase0) sa[j][1] = -1e30f;
                if (c0     > rbase1) sa[j][2] = -1e30f;
                if (c0 + 1 > rbase1) sa[j][3] = -1e30f;
            }
            mx0 = fmaxf(mx0, fmaxf(sa[j][0], sa[j][1]));
            mx1 = fmaxf(mx1, fmaxf(sa[j][2], sa[j][3]));
        }
        mx0 = fmaxf(mx0, __shfl_xor_sync(0xffffffffu, mx0, 1));
        mx0 = fmaxf(mx0, __shfl_xor_sync(0xffffffffu, mx0, 2));
        mx1 = fmaxf(mx1, __shfl_xor_sync(0xffffffffu, mx1, 1));
        mx1 = fmaxf(mx1, __shfl_xor_sync(0xffffffffu, mx1, 2));
        float mn0 = fmaxf(m0, mx0), mn1 = fmaxf(m1, mx1);
        float cr0 = fexp2((m0 - mn0) * L2E);
        float cr1 = fexp2((m1 - mn1) * L2E);
        m0 = mn0; m1 = mn1;

        // ---- exp + P fragments ----
        float su0 = 0.f, su1 = 0.f;
        uint32_t pah[4][4], pal[4][4];
        #pragma unroll
        for (int j = 0; j < 8; j++) {
            float p0 = fexp2((sa[j][0] - mn0) * L2E);
            float p1 = fexp2((sa[j][1] - mn0) * L2E);
            float p2 = fexp2((sa[j][2] - mn1) * L2E);
            float p3 = fexp2((sa[j][3] - mn1) * L2E);
            su0 += p0 + p1; su1 += p2 + p3;
            __nv_bfloat162 h01, h23, lo01, lo23;
            h01.x = __float2bfloat16(p0); h01.y = __float2bfloat16(p1);
            h23.x = __float2bfloat16(p2); h23.y = __float2bfloat16(p3);
            lo01.x = __float2bfloat16(p0 - __bfloat162float(h01.x));
            lo01.y = __float2bfloat16(p1 - __bfloat162float(h01.y));
            lo23.x = __float2bfloat16(p2 - __bfloat162float(h23.x));
            lo23.y = __float2bfloat16(p3 - __bfloat162float(h23.y));
            int t = j >> 1, hf = j & 1;
            pah[t][hf*2]   = *reinterpret_cast<uint32_t*>(&h01);
            pah[t][hf*2+1] = *reinterpret_cast<uint32_t*>(&h23);
            pal[t][hf*2]   = *reinterpret_cast<uint32_t*>(&lo01);
            pal[t][hf*2+1] = *reinterpret_cast<uint32_t*>(&lo23);
        }
        su0 += __shfl_xor_sync(0xffffffffu, su0, 1);
        su0 += __shfl_xor_sync(0xffffffffu, su0, 2);
        su1 += __shfl_xor_sync(0xffffffffu, su1, 1);
        su1 += __shfl_xor_sync(0xffffffffu, su1, 2);
        l0 = l0 * cr0 + su0;
        l1 = l1 * cr1 + su1;
        #pragma unroll
        for (int j = 0; j < 6; j++) {
            oacc[j][0] *= cr0; oacc[j][1] *= cr0;
            oacc[j][2] *= cr1; oacc[j][3] *= cr1;
        }

        // ---- O += P V ----
        #pragma unroll
        for (int np = 0; np < 3; np++) {
            #pragma unroll
            for (int t = 0; t < 4; t++) {
                uint32_t voff = (uint32_t)(np * 16 + brow) * VSTRD + t * 32 + bk16;
                uint32_t vh4[4], vl4[4];
                ldmat4(uVh + voff, vh4);
                ldmat4(uVl + voff, vl4);
                mma_bf16(oacc[2*np],   pah[t], vh4);     mma_bf16(oacc[2*np],   pah[t], vl4);
                mma_bf16(oacc[2*np],   pal[t], vh4);
                mma_bf16(oacc[2*np+1], pah[t], vh4+2);   mma_bf16(oacc[2*np+1], pah[t], vl4+2);
                mma_bf16(oacc[2*np+1], pal[t], vh4+2);
            }
        }
        __syncthreads();   // stage st free for reload next iteration
        st ^= 1;
    }

    // ---- epilogue: split-bf16 ctx directly ----
    float il0 = 1.0f / l0, il1 = 1.0f / l1;
    size_t base0 = ((size_t)b * TSZ + rbase0) * CSZ + h * HD;
    size_t base1 = ((size_t)b * TSZ + rbase1) * CSZ + h * HD;
    #pragma unroll
    for (int j = 0; j < 6; j++) {
        int dv = 8 * j + 2 * tig;
        float v00 = oacc[j][0] * il0, v01 = oacc[j][1] * il0;
        float v10 = oacc[j][2] * il1, v11 = oacc[j][3] * il1;
        __nv_bfloat162 h0, h1, lo0, lo1;
        h0.x = __float2bfloat16(v00); h0.y = __float2bfloat16(v01);
        h1.x = __float2bfloat16(v10); h1.y = __float2bfloat16(v11);
        lo0.x = __float2bfloat16(v00 - __bfloat162float(h0.x));
        lo0.y = __float2bfloat16(v01 - __bfloat162float(h0.y));
        lo1.x = __float2bfloat16(v10 - __bfloat162float(h1.x));
        lo1.y = __float2bfloat16(v11 - __bfloat162float(h1.y));
        *reinterpret_cast<__nv_bfloat162*>(g_chi + base0 + dv) = h0;
        *reinterpret_cast<__nv_bfloat162*>(g_clo + base0 + dv) = lo0;
        *reinterpret_cast<__nv_bfloat162*>(g_chi + base1 + dv) = h1;
        *reinterpret_cast<__nv_bfloat162*>(g_clo + base1 + dv) = lo1;
    }
}

// ---------------------------------------------------------------------------
extern "C" void kernel_launch(void* const* d_in, const int* in_sizes, int n_in,
                              void* d_out, int out_size)
{
    const float* X    = (const float*)d_in[0];
    const float* mask = (const float*)d_in[1];
    const float* Wq   = (const float*)d_in[2];
    const float* bq   = (const float*)d_in[3];
    const float* Wk   = (const float*)d_in[4];
    const float* bk   = (const float*)d_in[5];
    const float* Wv   = (const float*)d_in[6];
    const float* bv   = (const float*)d_in[7];
    const float* Wo   = (const float*)d_in[8];
    const float* bo   = (const float*)d_in[9];
    float* out = (float*)d_out;

    float *qb, *kb, *vb;
    cudaGetSymbolAddress((void**)&qb, g_q);
    cudaGetSymbolAddress((void**)&kb, g_k);
    cudaGetSymbolAddress((void**)&vb, g_v);
    __nv_bfloat16 *xhi, *xlo, *chi, *clo, *whi, *wlo;
    cudaGetSymbolAddress((void**)&xhi, g_xhi);
    cudaGetSymbolAddress((void**)&xlo, g_xlo);
    cudaGetSymbolAddress((void**)&chi, g_chi);
    cudaGetSymbolAddress((void**)&clo, g_clo);
    cudaGetSymbolAddress((void**)&whi, g_whi);
    cudaGetSymbolAddress((void**)&wlo, g_wlo);

    cudaFuncSetAttribute(gemm_mma_kernel,
                         cudaFuncAttributeMaxDynamicSharedMemorySize, GEMM_SMEM);
    cudaFuncSetAttribute(attn_mma_kernel,
                         cudaFuncAttributeMaxDynamicSharedMemorySize, ATTN_SMEM);

    // Split-bf16 conversions
    int xn4 = MSZ * CSZ / 4;
    conv_kernel<<<(xn4 + 255) / 256, 256>>>(X, xhi, xlo, xn4);
    int wn4 = CSZ * CSZ / 4;
    conv_kernel<<<(wn4 + 255) / 256, 256>>>(Wq, whi + 0*CSZ*CSZ, wlo + 0*CSZ*CSZ, wn4);
    conv_kernel<<<(wn4 + 255) / 256, 256>>>(Wk, whi + 1*CSZ*CSZ, wlo + 1*CSZ*CSZ, wn4);
    conv_kernel<<<(wn4 + 255) / 256, 256>>>(Wv, whi + 2*CSZ*CSZ, wlo + 2*CSZ*CSZ, wn4);
    conv_kernel<<<(wn4 + 255) / 256, 256>>>(Wo, whi + 3*CSZ*CSZ, wlo + 3*CSZ*CSZ, wn4);

    // QKV projections (HMMA) with head scatter -> fp32 q/k/v
    dim3 ggrid(CSZ / CTA_N, MSZ / CTA_M);   // (6, 64)
    gemm_mma_kernel<<<ggrid, 256, GEMM_SMEM>>>(xhi, xlo, whi + 0*CSZ*CSZ, wlo + 0*CSZ*CSZ, bq, qb, 1);
    gemm_mma_kernel<<<ggrid, 256, GEMM_SMEM>>>(xhi, xlo, whi + 1*CSZ*CSZ, wlo + 1*CSZ*CSZ, bk, kb, 1);
    gemm_mma_kernel<<<ggrid, 256, GEMM_SMEM>>>(xhi, xlo, whi + 2*CSZ*CSZ, wlo + 2*CSZ*CSZ, bv, vb, 1);

    // RoPE + scale + split-bf16 (Q/K), transpose + split (V)
    int pq_total = BH * TSZ * (HD / 2);
    prep_qk_kernel<<<(pq_total + 255) / 256, 256>>>();
    dim3 pvgrid(TSZ / 64, BH);
    prep_v_kernel<<<pvgrid, 256>>>();

    // Tensor-core flash attention -> chi/clo directly
    dim3 agrid(TSZ / 64, BH);   // (32, 64)
    attn_mma_kernel<<<agrid, 128, ATTN_SMEM>>>(mask);

    // O projection
    gemm_mma_kernel<<<ggrid, 256, GEMM_SMEM>>>(chi, clo, whi + 3*CSZ*CSZ, wlo + 3*CSZ*CSZ, bo, out, 0);
}

// round 8
// speedup vs baseline: 5.5983x; 1.7358x over previous
#include <cuda_runtime.h>
#include <cuda_fp16.h>
#include <cstdint>
#include <math.h>

#define BSZ 4
#define TSZ 2048
#define CSZ 768
#define NH  16
#define HD  48
#define MSZ (BSZ*TSZ)   // 8192
#define BH  (BSZ*NH)    // 64
#define L2E 1.4426950408889634f

// ---------------------------------------------------------------------------
// Scratch (device globals -> no allocation)
// ---------------------------------------------------------------------------
__device__ float g_q[BH*TSZ*HD];
__device__ float g_k[BH*TSZ*HD];
__device__ float g_v[BH*TSZ*HD];

__device__ __half g_xh[MSZ*CSZ];          // X in fp16
__device__ __half g_ch[MSZ*CSZ];          // ctx in fp16
__device__ __half g_wh[4][CSZ*CSZ];       // Wq,Wk,Wv,Wo in fp16

// attention operands (fp16)
__device__ __half g_qh[BH*TSZ*HD];
__device__ __half g_kh[BH*TSZ*HD];
__device__ __half g_vth[BH*HD*TSZ];       // V transposed [bh][dv][t]

// ---------------------------------------------------------------------------
// PTX helpers (compute_103-safe: mma.sync / ldmatrix / cp.async only)
// ---------------------------------------------------------------------------
__device__ __forceinline__ uint32_t smem_u32(const void* p) {
    uint32_t a;
    asm("{ .reg .u64 t; cvta.to.shared.u64 t, %1; cvt.u32.u64 %0, t; }"
        : "=r"(a) : "l"(p));
    return a;
}
__device__ __forceinline__ void cp_async16(uint32_t s, const void* g) {
    asm volatile("cp.async.ca.shared.global [%0], [%1], 16;" :: "r"(s), "l"(g));
}
#define CP_COMMIT() asm volatile("cp.async.commit_group;" ::: "memory")
#define CP_WAIT(n)  asm volatile("cp.async.wait_group %0;" :: "n"(n) : "memory")

__device__ __forceinline__ void ldmat4(uint32_t addr, uint32_t* r) {
    asm volatile("ldmatrix.sync.aligned.m8n8.x4.shared.b16 {%0,%1,%2,%3}, [%4];"
        : "=r"(r[0]), "=r"(r[1]), "=r"(r[2]), "=r"(r[3]) : "r"(addr));
}
__device__ __forceinline__ void mma_f16(float* d, const uint32_t* a, const uint32_t* b) {
    asm volatile("mma.sync.aligned.m16n8k16.row.col.f32.f16.f16.f32 "
        "{%0,%1,%2,%3}, {%4,%5,%6,%7}, {%8,%9}, {%0,%1,%2,%3};"
        : "+f"(d[0]), "+f"(d[1]), "+f"(d[2]), "+f"(d[3])
        : "r"(a[0]), "r"(a[1]), "r"(a[2]), "r"(a[3]), "r"(b[0]), "r"(b[1]));
}

// FMA-pipe exp2 (no MUFU)
__device__ __forceinline__ float fexp2(float t) {
    t = fmaxf(t, -126.0f);
    float fi = floorf(t);
    float f = t - fi;
    float p = 1.54035e-4f;
    p = fmaf(p, f, 1.33336e-3f);
    p = fmaf(p, f, 9.61813e-3f);
    p = fmaf(p, f, 5.55041e-2f);
    p = fmaf(p, f, 2.40227e-1f);
    p = fmaf(p, f, 6.93147e-1f);
    p = fmaf(p, f, 1.0f);
    int e = (int)fi;
    return __int_as_float(__float_as_int(p) + (e << 23));
}

// ---------------------------------------------------------------------------
// fp32 -> fp16
// ---------------------------------------------------------------------------
__global__ void __launch_bounds__(256)
conv_kernel(const float* __restrict__ in, __half* __restrict__ out, int n4)
{
    int i = blockIdx.x * blockDim.x + threadIdx.x;
    if (i >= n4) return;
    float4 x = reinterpret_cast<const float4*>(in)[i];
    __half2 h0; h0.x = __float2half(x.x); h0.y = __float2half(x.y);
    __half2 h1; h1.x = __float2half(x.z); h1.y = __float2half(x.w);
    reinterpret_cast<__half2*>(out)[2*i]   = h0;
    reinterpret_cast<__half2*>(out)[2*i+1] = h1;
}

// ---------------------------------------------------------------------------
// fp16 single-product GEMM: 256 threads, CTA 128x128, 8 warps of 64x32.
// out[m,n] = sum_k A[m,k]*W[n,k] + bias[n].  grid.z selects (W, bias, out).
// ---------------------------------------------------------------------------
#define CTA_M 128
#define CTA_N 128
#define KCH   32
#define NCH   (CSZ/KCH)        // 24
#define STRD  80               // 32 fp16 = 64B + 16B pad
#define A_BYTES (CTA_M*STRD)   // 10240
#define W_BYTES (CTA_N*STRD)   // 10240
#define STAGE_BYTES (A_BYTES + W_BYTES)      // 20480
#define GEMM_SMEM (2*STAGE_BYTES)            // 40960

__global__ void __launch_bounds__(256)
gemm_mma_kernel(const __half* __restrict__ A,
                const __half* __restrict__ W0, const __half* __restrict__ W1,
                const __half* __restrict__ W2,
                const float* __restrict__ b0, const float* __restrict__ b1,
                const float* __restrict__ b2,
                float* __restrict__ o0, float* __restrict__ o1,
                float* __restrict__ o2, int scatter)
{
    extern __shared__ char smem[];
    const int z = blockIdx.z;
    const __half* W = (z == 0) ? W0 : (z == 1) ? W1 : W2;
    const float* bias = (z == 0) ? b0 : (z == 1) ? b1 : b2;
    float* out = (z == 0) ? o0 : (z == 1) ? o1 : o2;

    const int tid  = threadIdx.x;
    const int wid  = tid >> 5;
    const int lane = tid & 31;
    const int m0 = blockIdx.y * CTA_M;
    const int n0 = blockIdx.x * CTA_N;
    const int wm = (wid & 1) * 64;
    const int wn = (wid >> 1) * 32;
    const uint32_t sbase = smem_u32(smem);

    float acc[4][4][4];
    #pragma unroll
    for (int a = 0; a < 4; a++)
        #pragma unroll
        for (int b = 0; b < 4; b++)
            #pragma unroll
            for (int c = 0; c < 4; c++) acc[a][b][c] = 0.f;

    auto load_stage = [&](int kc, int s) {
        uint32_t sb = sbase + s * STAGE_BYTES;
        int kk = kc * KCH;
        #pragma unroll
        for (int i = 0; i < 2; i++) {            // A: 512 x 16B
            int idx = i * 256 + tid;
            int row = idx >> 2, seg = idx & 3;
            cp_async16(sb + row * STRD + seg * 16,
                       A + (size_t)(m0 + row) * CSZ + kk + seg * 8);
        }
        #pragma unroll
        for (int i = 0; i < 2; i++) {            // W: 512 x 16B
            int idx = i * 256 + tid;
            int row = idx >> 2, seg = idx & 3;
            cp_async16(sb + A_BYTES + row * STRD + seg * 16,
                       W + (size_t)(n0 + row) * CSZ + kk + seg * 8);
        }
        CP_COMMIT();
    };

    load_stage(0, 0);
    int s = 0;

    const int l15 = lane & 15;
    const int lh16 = (lane >> 4) * 16;
    const int brow = ((lane >> 4) << 3) + (lane & 7);
    const int bk16 = ((lane >> 3) & 1) * 16;

    for (int kc = 0; kc < NCH; kc++) {
        if (kc + 1 < NCH) { load_stage(kc + 1, s ^ 1); CP_WAIT(1); }
        else             { CP_WAIT(0); }
        __syncthreads();

        uint32_t aB = sbase + s * STAGE_BYTES;
        uint32_t wB = aB + A_BYTES;

        #pragma unroll
        for (int ks = 0; ks < 2; ks++) {
            uint32_t aoff = (uint32_t)(wm + l15) * STRD + ks * 32 + lh16;
            uint32_t af[4][4];
            #pragma unroll
            for (int mt = 0; mt < 4; mt++)
                ldmat4(aB + aoff + mt * 16 * STRD, af[mt]);
            uint32_t boff = (uint32_t)(wn + brow) * STRD + ks * 32 + bk16;
            uint32_t bf[4][2];
            #pragma unroll
            for (int i = 0; i < 2; i++) {
                uint32_t r[4];
                ldmat4(wB + boff + i * 16 * STRD, r);
                bf[2*i][0] = r[0]; bf[2*i][1] = r[1];
                bf[2*i+1][0] = r[2]; bf[2*i+1][1] = r[3];
            }
            #pragma unroll
            for (int mt = 0; mt < 4; mt++)
                #pragma unroll
                for (int nt = 0; nt < 4; nt++)
                    mma_f16(acc[mt][nt], af[mt], bf[nt]);
        }
        __syncthreads();
        s ^= 1;
    }

    const int gid = lane >> 2, tig = lane & 3;
    #pragma unroll
    for (int mt = 0; mt < 4; mt++) {
        #pragma unroll
        for (int nt = 0; nt < 4; nt++) {
            int row = m0 + wm + mt * 16 + gid;
            int col = n0 + wn + nt * 8 + tig * 2;
            float v00 = acc[mt][nt][0] + bias[col];
            float v01 = acc[mt][nt][1] + bias[col + 1];
            float v10 = acc[mt][nt][2] + bias[col];
            float v11 = acc[mt][nt][3] + bias[col + 1];
            if (!scatter) {
                out[(size_t)row * CSZ + col]           = v00;
                out[(size_t)row * CSZ + col + 1]       = v01;
                out[(size_t)(row + 8) * CSZ + col]     = v10;
                out[(size_t)(row + 8) * CSZ + col + 1] = v11;
            } else {
                int b0i = row / TSZ, t0 = row % TSZ;
                int b1i = (row + 8) / TSZ, t1 = (row + 8) % TSZ;
                int h0 = col / HD, d0 = col % HD;
                int h1 = (col + 1) / HD, d1 = (col + 1) % HD;
                out[(((size_t)(b0i * NH + h0)) * TSZ + t0) * HD + d0] = v00;
                out[(((size_t)(b0i * NH + h1)) * TSZ + t0) * HD + d1] = v01;
                out[(((size_t)(b1i * NH + h0)) * TSZ + t1) * HD + d0] = v10;
                out[(((size_t)(b1i * NH + h1)) * TSZ + t1) * HD + d1] = v11;
            }
        }
    }
}

// ---------------------------------------------------------------------------
// prep_qk: RoPE + scale(Q) -> fp16 Q/K
// ---------------------------------------------------------------------------
__global__ void __launch_bounds__(256)
prep_qk_kernel()
{
    const int total = BH * TSZ * (HD / 2);
    int idx = blockIdx.x * blockDim.x + threadIdx.x;
    if (idx >= total) return;
    int i   = idx % (HD / 2);
    int row = idx / (HD / 2);
    int t   = row % TSZ;

    float inv_freq = expf(-((float)i / 24.0f) * 9.210340371976184f);
    float ang = (float)t * inv_freq;
    float s, c;
    sincosf(ang, &s, &c);

    const float scale = 0.14433756729740643f;
    const float* q = g_q + (size_t)row * HD;
    const float* k = g_k + (size_t)row * HD;
    float q1 = q[i], q2 = q[i + 24];
    float k1 = k[i], k2 = k[i + 24];

    size_t o = (size_t)row * HD;
    g_qh[o+i]    = __float2half((q1 * c - q2 * s) * scale);
    g_qh[o+i+24] = __float2half((q2 * c + q1 * s) * scale);
    g_kh[o+i]    = __float2half(k1 * c - k2 * s);
    g_kh[o+i+24] = __float2half(k2 * c + k1 * s);
}

// ---------------------------------------------------------------------------
// prep_v: transpose V per head -> [bh][dv][t] fp16
// ---------------------------------------------------------------------------
__global__ void __launch_bounds__(256)
prep_v_kernel()
{
    __shared__ float sv[64][49];
    const int bh = blockIdx.y;
    const int t0 = blockIdx.x * 64;
    const int tid = threadIdx.x;

    const float* src = g_v + ((size_t)bh * TSZ + t0) * HD;
    for (int e = tid; e < 64 * HD; e += 256)
        sv[e / HD][e % HD] = src[e];
    __syncthreads();
    for (int e = tid; e < 64 * HD; e += 256) {
        int dv = e / 64, j = e % 64;
        g_vth[((size_t)bh * HD + dv) * TSZ + t0 + j] = __float2half(sv[j][dv]);
    }
}

// ---------------------------------------------------------------------------
// Tensor-core causal flash attention, fp16 single-product, double-buffered KV.
// CTA: 64 q rows, 4 warps x 16 rows, kv tiles of 64. fp16 ctx output.
// ---------------------------------------------------------------------------
#define KSTRD 112          // 48 fp16 = 96B + 16 pad
#define VSTRD 144          // 64 fp16 = 128B + 16 pad
#define QTB   (64*KSTRD)   // 7168
#define KTB   (64*KSTRD)   // 7168
#define VTB   (HD*VSTRD)   // 6912
#define O_KV(s)  (QTB + (s) * (KTB + VTB))
#define O_MS(s)  (QTB + 2*(KTB + VTB) + (s) * 256)
#define ATTN_SMEM (QTB + 2*(KTB + VTB) + 512)   // 35840

__global__ void __launch_bounds__(128)
attn_mma_kernel(const float* __restrict__ mask)
{
    extern __shared__ char asm_[];
    const uint32_t sbase = smem_u32(asm_);
    float* sMs[2] = { (float*)(asm_ + O_MS(0)), (float*)(asm_ + O_MS(1)) };

    const int tid = threadIdx.x, wid = tid >> 5, lane = tid & 31;
    const int qt = gridDim.x - 1 - blockIdx.x;   // heavy CTAs first
    const int bh = blockIdx.y;
    const int b  = bh >> 4, h = bh & 15;
    const int q0 = qt * 64;

    const uint32_t uQ = sbase;
    const float* mrow = mask + b * TSZ;

    // ---- load Q tile ----
    {
        const __half* qg = g_qh + ((size_t)bh * TSZ + q0) * HD;
        for (int i = tid; i < 384; i += 128) {
            int r = i / 6, s6 = i % 6;
            cp_async16(uQ + r * KSTRD + s6 * 16, qg + r * HD + s6 * 8);
        }
        CP_COMMIT(); CP_WAIT(0);
    }
    __syncthreads();

    // ---- Q fragments in regs ----
    const int l15 = lane & 15, lh16 = (lane >> 4) * 16;
    uint32_t qf[3][4];
    #pragma unroll
    for (int k3 = 0; k3 < 3; k3++)
        ldmat4(uQ + (uint32_t)(wid * 16 + l15) * KSTRD + k3 * 32 + lh16, qf[k3]);

    auto load_kv = [&](int kt, int s) {
        uint32_t kB = sbase + O_KV(s), vB = kB + KTB;
        const __half* kg = g_kh + ((size_t)bh * TSZ + kt * 64) * HD;
        for (int i = tid; i < 384; i += 128) {
            int r = i / 6, s6 = i % 6;
            cp_async16(kB + r * KSTRD + s6 * 16, kg + r * HD + s6 * 8);
        }
        const __half* vg = g_vth + (size_t)bh * HD * TSZ + kt * 64;
        for (int i = tid; i < 384; i += 128) {
            int r = i / 8, s8 = i % 8;
            cp_async16(vB + r * VSTRD + s8 * 16, vg + (size_t)r * TSZ + s8 * 8);
        }
        if (tid < 64) sMs[s][tid] = (1.0f - mrow[kt * 64 + tid]) * -10000.0f;
        CP_COMMIT();
    };

    float oacc[6][4];
    #pragma unroll
    for (int j = 0; j < 6; j++)
        #pragma unroll
        for (int c = 0; c < 4; c++) oacc[j][c] = 0.f;
    float m0 = -1e30f, m1 = -1e30f, l0 = 0.f, l1 = 0.f;

    const int brow = ((lane >> 4) << 3) + (lane & 7);
    const int bk16 = ((lane >> 3) & 1) * 16;
    const int gid = lane >> 2, tig = lane & 3;
    const int rbase0 = q0 + wid * 16 + gid;
    const int rbase1 = rbase0 + 8;

    load_kv(0, 0);
    int st = 0;

    for (int kt = 0; kt <= qt; kt++) {
        if (kt < qt) { load_kv(kt + 1, st ^ 1); CP_WAIT(1); }
        else         { CP_WAIT(0); }
        __syncthreads();

        uint32_t uK = sbase + O_KV(st);
        uint32_t uV = uK + KTB;
        float* ms = sMs[st];

        // ---- S = Q K^T ----
        float sa[8][4];
        #pragma unroll
        for (int j = 0; j < 8; j++)
            #pragma unroll
            for (int c = 0; c < 4; c++) sa[j][c] = 0.f;

        #pragma unroll
        for (int jp = 0; jp < 4; jp++) {
            #pragma unroll
            for (int k3 = 0; k3 < 3; k3++) {
                uint32_t kf[4];
                ldmat4(uK + (uint32_t)(jp * 16 + brow) * KSTRD + k3 * 32 + bk16, kf);
                mma_f16(sa[2*jp],   qf[k3], kf);
                mma_f16(sa[2*jp+1], qf[k3], kf + 2);
            }
        }

        // ---- mask + row stats ----
        const bool diag = (kt == qt);
        float mx0 = -1e30f, mx1 = -1e30f;
        #pragma unroll
        for (int j = 0; j < 8; j++) {
            int c0 = kt * 64 + 8 * j + 2 * tig;
            float ms0 = ms[8*j + 2*tig], ms1 = ms[8*j + 2*tig + 1];
            sa[j][0] += ms0; sa[j][1] += ms1; sa[j][2] += ms0; sa[j][3] += ms1;
            if (diag) {
                if (c0     > rbase0) sa[j][0] = -1e30f;
                if (c0 + 1 > rbase0) sa[j][1] = -1e30f;
                if (c0     > rbase1) sa[j][2] = -1e30f;
                if (c0 + 1 > rbase1) sa[j][3] = -1e30f;
            }
            mx0 = fmaxf(mx0, fmaxf(sa[j][0], sa[j][1]));
            mx1 = fmaxf(mx1, fmaxf(sa[j][2], sa[j][3]));
        }
        mx0 = fmaxf(mx0, __shfl_xor_sync(0xffffffffu, mx0, 1));
        mx0 = fmaxf(mx0, __shfl_xor_sync(0xffffffffu, mx0, 2));
        mx1 = fmaxf(mx1, __shfl_xor_sync(0xffffffffu, mx1, 1));
        mx1 = fmaxf(mx1, __shfl_xor_sync(0xffffffffu, mx1, 2));
        float mn0 = fmaxf(m0, mx0), mn1 = fmaxf(m1, mx1);
        float cr0 = fexp2((m0 - mn0) * L2E);
        float cr1 = fexp2((m1 - mn1) * L2E);
        m0 = mn0; m1 = mn1;

        // ---- exp + P fragments (fp16) ----
        float su0 = 0.f, su1 = 0.f;
        uint32_t pa[4][4];
        #pragma unroll
        for (int j = 0; j < 8; j++) {
            float p0 = fexp2((sa[j][0] - mn0) * L2E);
            float p1 = fexp2((sa[j][1] - mn0) * L2E);
            float p2 = fexp2((sa[j][2] - mn1) * L2E);
            float p3 = fexp2((sa[j][3] - mn1) * L2E);
            su0 += p0 + p1; su1 += p2 + p3;
            __half2 h01, h23;
            h01.x = __float2half(p0); h01.y = __float2half(p1);
            h23.x = __float2half(p2); h23.y = __float2half(p3);
            int t = j >> 1, hf = j & 1;
            pa[t][hf*2]   = *reinterpret_cast<uint32_t*>(&h01);
            pa[t][hf*2+1] = *reinterpret_cast<uint32_t*>(&h23);
        }
        su0 += __shfl_xor_sync(0xffffffffu, su0, 1);
        su0 += __shfl_xor_sync(0xffffffffu, su0, 2);
        su1 += __shfl_xor_sync(0xffffffffu, su1, 1);
        su1 += __shfl_xor_sync(0xffffffffu, su1, 2);
        l0 = l0 * cr0 + su0;
        l1 = l1 * cr1 + su1;
        #pragma unroll
        for (int j = 0; j < 6; j++) {
            oacc[j][0] *= cr0; oacc[j][1] *= cr0;
            oacc[j][2] *= cr1; oacc[j][3] *= cr1;
        }

        // ---- O += P V ----
        #pragma unroll
        for (int np = 0; np < 3; np++) {
            #pragma unroll
            for (int t = 0; t < 4; t++) {
                uint32_t vf[4];
                ldmat4(uV + (uint32_t)(np * 16 + brow) * VSTRD + t * 32 + bk16, vf);
                mma_f16(oacc[2*np],   pa[t], vf);
                mma_f16(oacc[2*np+1], pa[t], vf + 2);
            }
        }
        __syncthreads();
        st ^= 1;
    }

    // ---- epilogue: fp16 ctx ----
    float il0 = 1.0f / l0, il1 = 1.0f / l1;
    size_t base0 = ((size_t)b * TSZ + rbase0) * CSZ + h * HD;
    size_t base1 = ((size_t)b * TSZ + rbase1) * CSZ + h * HD;
    #pragma unroll
    for (int j = 0; j < 6; j++) {
        int dv = 8 * j + 2 * tig;
        __half2 h0, h1;
        h0.x = __float2half(oacc[j][0] * il0); h0.y = __float2half(oacc[j][1] * il0);
        h1.x = __float2half(oacc[j][2] * il1); h1.y = __float2half(oacc[j][3] * il1);
        *reinterpret_cast<__half2*>(g_ch + base0 + dv) = h0;
        *reinterpret_cast<__half2*>(g_ch + base1 + dv) = h1;
    }
}

// ---------------------------------------------------------------------------
extern "C" void kernel_launch(void* const* d_in, const int* in_sizes, int n_in,
                              void* d_out, int out_size)
{
    const float* X    = (const float*)d_in[0];
    const float* mask = (const float*)d_in[1];
    const float* Wq   = (const float*)d_in[2];
    const float* bq   = (const float*)d_in[3];
    const float* Wk   = (const float*)d_in[4];
    const float* bk   = (const float*)d_in[5];
    const float* Wv   = (const float*)d_in[6];
    const float* bv   = (const float*)d_in[7];
    const float* Wo   = (const float*)d_in[8];
    const float* bo   = (const float*)d_in[9];
    float* out = (float*)d_out;

    float *qb, *kb, *vb;
    cudaGetSymbolAddress((void**)&qb, g_q);
    cudaGetSymbolAddress((void**)&kb, g_k);
    cudaGetSymbolAddress((void**)&vb, g_v);
    __half *xh, *ch, *wh;
    cudaGetSymbolAddress((void**)&xh, g_xh);
    cudaGetSymbolAddress((void**)&ch, g_ch);
    cudaGetSymbolAddress((void**)&wh, g_wh);

    cudaFuncSetAttribute(gemm_mma_kernel,
                         cudaFuncAttributeMaxDynamicSharedMemorySize, GEMM_SMEM);
    cudaFuncSetAttribute(attn_mma_kernel,
                         cudaFuncAttributeMaxDynamicSharedMemorySize, ATTN_SMEM);

    // fp16 conversions
    int xn4 = MSZ * CSZ / 4;
    conv_kernel<<<(xn4 + 255) / 256, 256>>>(X, xh, xn4);
    int wn4 = CSZ * CSZ / 4;
    conv_kernel<<<(wn4 + 255) / 256, 256>>>(Wq, wh + 0*CSZ*CSZ, wn4);
    conv_kernel<<<(wn4 + 255) / 256, 256>>>(Wk, wh + 1*CSZ*CSZ, wn4);
    conv_kernel<<<(wn4 + 255) / 256, 256>>>(Wv, wh + 2*CSZ*CSZ, wn4);
    conv_kernel<<<(wn4 + 255) / 256, 256>>>(Wo, wh + 3*CSZ*CSZ, wn4);

    // Fused QKV projections (grid.z = 3) with head scatter -> fp32 q/k/v
    dim3 ggrid(CSZ / CTA_N, MSZ / CTA_M, 3);   // (6, 64, 3)
    gemm_mma_kernel<<<ggrid, 256, GEMM_SMEM>>>(
        xh, wh + 0*CSZ*CSZ, wh + 1*CSZ*CSZ, wh + 2*CSZ*CSZ,
        bq, bk, bv, qb, kb, vb, 1);

    // RoPE + scale -> fp16 q/k; transpose -> fp16 vt
    int pq_total = BH * TSZ * (HD / 2);
    prep_qk_kernel<<<(pq_total + 255) / 256, 256>>>();
    dim3 pvgrid(TSZ / 64, BH);
    prep_v_kernel<<<pvgrid, 256>>>();

    // Tensor-core flash attention -> fp16 ctx
    dim3 agrid(TSZ / 64, BH);   // (32, 64)
    attn_mma_kernel<<<agrid, 128, ATTN_SMEM>>>(mask);

    // O projection
    dim3 ogrid(CSZ / CTA_N, MSZ / CTA_M, 1);
    gemm_mma_kernel<<<ogrid, 256, GEMM_SMEM>>>(
        ch, wh + 3*CSZ*CSZ, wh + 3*CSZ*CSZ, wh + 3*CSZ*CSZ,
        bo, bo, bo, out, out, out, 0);
}